// round 11
// baseline (speedup 1.0000x reference)
#include <cuda_runtime.h>
#include <cuda_bf16.h>
#include <cstdint>

#define NB 4
#define NT 2048
#define NC 1024
#define NH 16
#define NHS 64

// ---------------- scratch (static device globals) ---------------------------
__device__ float g_v[(size_t)NB * NH * NT * NHS];
__device__ __nv_bfloat16 g_qh[(size_t)NB * NH * NT * NHS];
__device__ __nv_bfloat16 g_ql[(size_t)NB * NH * NT * NHS];
__device__ __nv_bfloat16 g_kh[(size_t)NB * NH * NT * NHS];
__device__ __nv_bfloat16 g_kl[(size_t)NB * NH * NT * NHS];
__device__ __nv_bfloat16 g_xh[(size_t)NB * NT * NC];   // x split; reused for attn-out
__device__ __nv_bfloat16 g_xl[(size_t)NB * NT * NC];
__device__ __nv_bfloat16 g_wh[(size_t)3 * NC * NC];    // Wq|Wk|Wv rows concat
__device__ __nv_bfloat16 g_wl[(size_t)3 * NC * NC];
__device__ __nv_bfloat16 g_woh[(size_t)NC * NC];
__device__ __nv_bfloat16 g_wol[(size_t)NC * NC];

// ---------------- helpers ---------------------------------------------------
__device__ __forceinline__ void mma16(float* d, const uint32_t* a, uint32_t b0, uint32_t b1) {
    asm volatile(
        "mma.sync.aligned.m16n8k16.row.col.f32.bf16.bf16.f32 "
        "{%0,%1,%2,%3}, {%4,%5,%6,%7}, {%8,%9}, {%0,%1,%2,%3};"
        : "+f"(d[0]), "+f"(d[1]), "+f"(d[2]), "+f"(d[3])
        : "r"(a[0]), "r"(a[1]), "r"(a[2]), "r"(a[3]), "r"(b0), "r"(b1));
}
__device__ __forceinline__ void ldsm4(uint32_t* r, uint32_t addr) {
    asm volatile("ldmatrix.sync.aligned.m8n8.x4.shared.b16 {%0,%1,%2,%3}, [%4];"
                 : "=r"(r[0]), "=r"(r[1]), "=r"(r[2]), "=r"(r[3]) : "r"(addr));
}
__device__ __forceinline__ void split_pack(float a, float b, uint32_t& h, uint32_t& l) {
    __nv_bfloat16 ha = __float2bfloat16(a), hb = __float2bfloat16(b);
    __nv_bfloat162 th; th.x = ha; th.y = hb;
    h = *(uint32_t*)&th;
    __nv_bfloat162 tl;
    tl.x = __float2bfloat16(a - __bfloat162float(ha));
    tl.y = __float2bfloat16(b - __bfloat162float(hb));
    l = *(uint32_t*)&tl;
}
#define CPA16(dst, src) \
    asm volatile("cp.async.cg.shared.global [%0], [%1], 16;" :: "r"(dst), "l"(src))
#define CPA_COMMIT() asm volatile("cp.async.commit_group;" ::: "memory")
#define CPA_WAIT2() asm volatile("cp.async.wait_group 2;" ::: "memory")
#define CPA_WAIT1() asm volatile("cp.async.wait_group 1;" ::: "memory")
#define CPA_WAIT0() asm volatile("cp.async.wait_group 0;" ::: "memory")

// ---------------- fused split: fp32 -> bf16 hi/lo for all 5 tensors ---------
__global__ void __launch_bounds__(256) split_all_kernel(
    const float* __restrict__ x,  const float* __restrict__ Wq,
    const float* __restrict__ Wk, const float* __restrict__ Wv,
    const float* __restrict__ Wo)
{
    const size_t XN = (size_t)NB * NT * NC;   // 8M
    const size_t WN = (size_t)NC * NC;        // 1M
    size_t i = ((size_t)blockIdx.x * 256 + threadIdx.x) * 4;
    const float* src;
    __nv_bfloat16 *dh, *dl;
    size_t off;
    if (i < XN)               { src = x;  dh = g_xh;          dl = g_xl;          off = i; }
    else if (i < XN + WN)     { src = Wq; dh = g_wh;          dl = g_wl;          off = i - XN; }
    else if (i < XN + 2 * WN) { src = Wk; dh = g_wh + WN;     dl = g_wl + WN;     off = i - XN - WN; }
    else if (i < XN + 3 * WN) { src = Wv; dh = g_wh + 2 * WN; dl = g_wl + 2 * WN; off = i - XN - 2 * WN; }
    else                      { src = Wo; dh = g_woh;         dl = g_wol;         off = i - XN - 3 * WN; }
    float4 v = *(const float4*)(src + off);
    uint32_t h0, l0, h1, l1;
    split_pack(v.x, v.y, h0, l0);
    split_pack(v.z, v.w, h1, l1);
    *(uint32_t*)(dh + off) = h0; *(uint32_t*)(dh + off + 2) = h1;
    *(uint32_t*)(dl + off) = l0; *(uint32_t*)(dl + off + 2) = l1;
}

// ---------------- GEMM: C = A(Mx1024) * B(Nx1024)^T, 3xBF16 ----------------
// 128x256 CTA tile, warp tile 64x64 (2x4 warps), K-chunk 32, 3-stage cp.async,
// ldmatrix fragment loads. 1 CTA/SM (184KB smem), compute-bound by design.
// Stage layout (u32): Ah[128*20] | Al[128*20] | Bh[256*20] | Bl[256*20] = 15360
static constexpr int G_STG = 15360;              // u32 per stage
static constexpr int GEMM_SMEM = 3 * G_STG * 4;  // 184320 B

template <int MODE>
__global__ void __launch_bounds__(256) gemm_bf16_kernel(
    const float* __restrict__ bias, float* __restrict__ Out)
{
    extern __shared__ uint32_t su[];

    const int tid = threadIdx.x;
    const int warp = tid >> 5, lane = tid & 31;
    const int g = lane >> 2, tg = lane & 3;
    const int wm = warp >> 2, wn = warp & 3;      // 2x4 warps, warp tile 64x64
    const int m0 = blockIdx.y * 128;
    const int n0 = blockIdx.x * 256;

    const __nv_bfloat16* Ah = g_xh;
    const __nv_bfloat16* Al = g_xl;
    const __nv_bfloat16* Bh = (MODE == 0) ? g_wh : g_woh;
    const __nv_bfloat16* Bl = (MODE == 0) ? g_wl : g_wol;

    float acc[4][8][4];
#pragma unroll
    for (int a = 0; a < 4; a++)
#pragma unroll
        for (int b = 0; b < 8; b++)
#pragma unroll
            for (int c = 0; c < 4; c++) acc[a][b][c] = 0.f;

    const int lr = tid >> 1;            // 0..127
    const int lc = (tid & 1) * 8;       // u32 col base 0 or 8
    const __nv_bfloat16* pA_h  = Ah + (size_t)(m0 + lr) * NC + lc * 2;
    const __nv_bfloat16* pA_l  = Al + (size_t)(m0 + lr) * NC + lc * 2;
    const __nv_bfloat16* pB_h0 = Bh + (size_t)(n0 + lr) * NC + lc * 2;
    const __nv_bfloat16* pB_h1 = Bh + (size_t)(n0 + 128 + lr) * NC + lc * 2;
    const __nv_bfloat16* pB_l0 = Bl + (size_t)(n0 + lr) * NC + lc * 2;
    const __nv_bfloat16* pB_l1 = Bl + (size_t)(n0 + 128 + lr) * NC + lc * 2;
    const uint32_t sb = (uint32_t)__cvta_generic_to_shared(su);
    const uint32_t sA = sb + (lr * 20 + lc) * 4;          // Ah slot of this thread

    // ldmatrix lane addressing
    const int lm = lane & 7, sel = lane >> 3;
    const int rowA = lm + ((sel & 1) << 3), colA = (sel & 2) << 1;
    const int rowB = lm + ((sel & 2) << 2), colB = (sel & 1) << 2;
    const uint32_t aH0 = sb + ((wm * 64 + rowA) * 20 + colA) * 4;
    const uint32_t aL0 = aH0 + 2560 * 4;
    const uint32_t bH0 = sb + 5120 * 4 + ((wn * 64 + rowB) * 20 + colB) * 4;
    const uint32_t bL0 = bH0 + 5120 * 4;

    // Per chunk per thread: 12 x 16B cp.async (A hi/lo 4, B hi/lo 8)
#define G_LOAD(S, KT)                                                          \
    {                                                                          \
        uint32_t dA = sA + (S) * (G_STG * 4);                                  \
        CPA16(dA,              pA_h  + (KT));                                  \
        CPA16(dA + 16,         pA_h  + (KT) + 8);                              \
        CPA16(dA + 10240,      pA_l  + (KT));                                  \
        CPA16(dA + 10240 + 16, pA_l  + (KT) + 8);                              \
        uint32_t dB = dA + 20480;                                              \
        CPA16(dB,              pB_h0 + (KT));                                  \
        CPA16(dB + 16,         pB_h0 + (KT) + 8);                              \
        CPA16(dB + 10240,      pB_h1 + (KT));                                  \
        CPA16(dB + 10240 + 16, pB_h1 + (KT) + 8);                              \
        CPA16(dB + 20480,      pB_l0 + (KT));                                  \
        CPA16(dB + 20480 + 16, pB_l0 + (KT) + 8);                              \
        CPA16(dB + 30720,      pB_l1 + (KT));                                  \
        CPA16(dB + 30720 + 16, pB_l1 + (KT) + 8);                              \
        CPA_COMMIT();                                                          \
    }

    G_LOAD(0, 0);
    G_LOAD(1, 32);

    int stage = 0;
    for (int c = 0; c < 32; c++) {
        if (c + 2 < 32)      { G_LOAD((c + 2) % 3, (c + 2) * 32); CPA_WAIT2(); }
        else if (c + 1 < 32) { CPA_WAIT1(); }
        else                 { CPA_WAIT0(); }
        __syncthreads();
        const uint32_t stg = stage * (G_STG * 4);

#pragma unroll
        for (int ks = 0; ks < 2; ks++) {
            const uint32_t ko = stg + ks * 32;
            uint32_t ah[4][4], al[4][4];
#pragma unroll
            for (int mt = 0; mt < 4; mt++) {
                ldsm4(ah[mt], aH0 + ko + mt * 1280);
                ldsm4(al[mt], aL0 + ko + mt * 1280);
            }
#pragma unroll
            for (int j = 0; j < 4; j++) {
                uint32_t bh[4], bl[4];
                ldsm4(bh, bH0 + ko + j * 1280);
                ldsm4(bl, bL0 + ko + j * 1280);
#pragma unroll
                for (int mt = 0; mt < 4; mt++) {
                    mma16(acc[mt][2 * j],     ah[mt], bh[0], bh[1]);
                    mma16(acc[mt][2 * j],     al[mt], bh[0], bh[1]);
                    mma16(acc[mt][2 * j],     ah[mt], bl[0], bl[1]);
                    mma16(acc[mt][2 * j + 1], ah[mt], bh[2], bh[3]);
                    mma16(acc[mt][2 * j + 1], al[mt], bh[2], bh[3]);
                    mma16(acc[mt][2 * j + 1], ah[mt], bl[2], bl[3]);
                }
            }
        }
        __syncthreads();
        if (++stage == 3) stage = 0;
    }

    // epilogue
#pragma unroll
    for (int mt = 0; mt < 4; mt++) {
        int row = m0 + wm * 64 + mt * 16 + g;
#pragma unroll
        for (int nt = 0; nt < 8; nt++) {
            int colg = n0 + wn * 64 + nt * 8 + 2 * tg;
            if (MODE == 0) {
                int sl = colg >> 10, cc = colg & 1023;
                int h = cc >> 6, d = cc & 63;
                int b = row >> 11, t = row & (NT - 1);
                size_t off = (((size_t)(b * NH + h) * NT) + t) * NHS + d;
                if (sl == 2) {
                    *(float2*)(g_v + off) = make_float2(acc[mt][nt][0], acc[mt][nt][1]);
                    *(float2*)(g_v + off + 8 * NHS) = make_float2(acc[mt][nt][2], acc[mt][nt][3]);
                } else {
                    float sc = (sl == 0) ? 8.f : 1.f;   // pre-scale Q by sqrt(HS)
                    __nv_bfloat16* dh = (sl == 0) ? g_qh : g_kh;
                    __nv_bfloat16* dl = (sl == 0) ? g_ql : g_kl;
                    uint32_t ph, pl;
                    split_pack(acc[mt][nt][0] * sc, acc[mt][nt][1] * sc, ph, pl);
                    *(uint32_t*)(dh + off) = ph;
                    *(uint32_t*)(dl + off) = pl;
                    split_pack(acc[mt][nt][2] * sc, acc[mt][nt][3] * sc, ph, pl);
                    *(uint32_t*)(dh + off + 8 * NHS) = ph;
                    *(uint32_t*)(dl + off + 8 * NHS) = pl;
                }
            } else {
                float2 bv = *(const float2*)(bias + colg);
                *(float2*)(Out + (size_t)row * NC + colg) =
                    make_float2(acc[mt][nt][0] + bv.x, acc[mt][nt][1] + bv.y);
                *(float2*)(Out + (size_t)(row + 8) * NC + colg) =
                    make_float2(acc[mt][nt][2] + bv.x, acc[mt][nt][3] + bv.y);
            }
        }
    }
}

// ---------------- flash attention (causal), 3xBF16 + ldmatrix (unchanged) ---
__global__ void __launch_bounds__(256, 2) flash_attn_kernel()
{
    extern __shared__ uint32_t su[];
    uint32_t* sQh = su;            // 128*36
    uint32_t* sQl = su + 4608;
    uint32_t* sKh = su + 9216;     // 32*36
    uint32_t* sKl = su + 10368;
    uint32_t* sVh = su + 11520;    // 64*20
    uint32_t* sVl = su + 12800;
    uint32_t* sPh = su + 14080;    // 128*20
    uint32_t* sPl = su + 16640;    // total 19200 u32

    const int tid = threadIdx.x;
    const int warp = tid >> 5, lane = tid & 31;
    const int g = lane >> 2, tg = lane & 3;
    const int qi = (int)gridDim.x - 1 - (int)blockIdx.x;   // longest first
    const int bh = blockIdx.y;

    const size_t base = (size_t)bh * NT * NHS;
    const __nv_bfloat16* Qhg = g_qh + base + (size_t)qi * 128 * NHS;
    const __nv_bfloat16* Qlg = g_ql + base + (size_t)qi * 128 * NHS;
    const __nv_bfloat16* Khg = g_kh + base;
    const __nv_bfloat16* Klg = g_kl + base;
    const float* Vg = g_v + base;

    const uint32_t sb = (uint32_t)__cvta_generic_to_shared(su);
    const int lm = lane & 7, sel = lane >> 3;
    const int rowA = lm + ((sel & 1) << 3), colA = (sel & 2) << 1;
    const int rowB = lm + ((sel & 2) << 2), colB = (sel & 1) << 2;
    const uint32_t qH0 = sb + ((warp * 16 + rowA) * 36 + colA) * 4;
    const uint32_t qL0 = qH0 + 4608 * 4;
    const uint32_t kH0 = sb + 9216 * 4 + (rowB * 36 + colB) * 4;
    const uint32_t kL0 = kH0 + 1152 * 4;
    const uint32_t vH0 = sb + 11520 * 4 + (rowB * 20 + colB) * 4;
    const uint32_t vL0 = vH0 + 1280 * 4;
    const uint32_t pH0 = sb + 14080 * 4 + ((warp * 16 + rowA) * 20 + colA) * 4;
    const uint32_t pL0 = pH0 + 2560 * 4;

    {
        int r = tid >> 1, cc = (tid & 1) * 16;
#pragma unroll
        for (int j = 0; j < 4; j++) {
            int eo = (cc + 4 * j) * 2;
            *(uint4*)&sQh[r * 36 + cc + 4 * j] = *(const uint4*)(Qhg + r * NHS + eo);
            *(uint4*)&sQl[r * 36 + cc + 4 * j] = *(const uint4*)(Qlg + r * NHS + eo);
        }
    }

    float o[8][4];
#pragma unroll
    for (int i = 0; i < 8; i++)
#pragma unroll
        for (int j = 0; j < 4; j++) o[i][j] = 0.f;
    float mr[2] = {-1e30f, -1e30f}, lsum[2] = {0.f, 0.f};

    const int row0 = qi * 128 + warp * 16 + g;
    const int nkt = 4 * qi + 4;

    const int kr = tid >> 3, kc = (tid & 7) * 4;
    const int vd = tid & 63, vq = tid >> 6;
    uint4 rkh, rkl;
    float rv0[4], rv1[4];
#define LD_KV(KT)                                                                  \
    {                                                                              \
        rkh = *(const uint4*)(Khg + (size_t)((KT) * 32 + kr) * NHS + kc * 2);      \
        rkl = *(const uint4*)(Klg + (size_t)((KT) * 32 + kr) * NHS + kc * 2);      \
        _Pragma("unroll") for (int i = 0; i < 4; i++) {                            \
            int kp = vq * 4 + i;                                                   \
            rv0[i] = Vg[(size_t)((KT) * 32 + 2 * kp) * NHS + vd];                  \
            rv1[i] = Vg[(size_t)((KT) * 32 + 2 * kp + 1) * NHS + vd];              \
        }                                                                          \
    }
    LD_KV(0);

    for (int kt = 0; kt < nkt; kt++) {
        __syncthreads();
        *(uint4*)&sKh[kr * 36 + kc] = rkh;
        *(uint4*)&sKl[kr * 36 + kc] = rkl;
        {
            uint4 vh4, vl4;
            split_pack(rv0[0], rv1[0], vh4.x, vl4.x);
            split_pack(rv0[1], rv1[1], vh4.y, vl4.y);
            split_pack(rv0[2], rv1[2], vh4.z, vl4.z);
            split_pack(rv0[3], rv1[3], vh4.w, vl4.w);
            *(uint4*)&sVh[vd * 20 + vq * 4] = vh4;
            *(uint4*)&sVl[vd * 20 + vq * 4] = vl4;
        }
        __syncthreads();
        if (kt + 1 < nkt) LD_KV(kt + 1);

        if (kt * 32 > qi * 128 + warp * 16 + 15) continue;

        float s[4][4];
#pragma unroll
        for (int i = 0; i < 4; i++)
#pragma unroll
            for (int j = 0; j < 4; j++) s[i][j] = 0.f;

#pragma unroll
        for (int ks = 0; ks < 4; ks++) {
            const uint32_t ko = ks * 32;
            uint32_t qh[4], ql[4];
            ldsm4(qh, qH0 + ko);
            ldsm4(ql, qL0 + ko);
#pragma unroll
            for (int j = 0; j < 2; j++) {
                uint32_t kh[4], kl[4];
                ldsm4(kh, kH0 + ko + j * 2304);
                ldsm4(kl, kL0 + ko + j * 2304);
                mma16(s[2 * j],     qh, kh[0], kh[1]);
                mma16(s[2 * j],     ql, kh[0], kh[1]);
                mma16(s[2 * j],     qh, kl[0], kl[1]);
                mma16(s[2 * j + 1], qh, kh[2], kh[3]);
                mma16(s[2 * j + 1], ql, kh[2], kh[3]);
                mma16(s[2 * j + 1], qh, kl[2], kl[3]);
            }
        }

        if (kt * 32 + 31 > qi * 128 + warp * 16) {
#pragma unroll
            for (int nt = 0; nt < 4; nt++)
#pragma unroll
                for (int c = 0; c < 4; c++) {
                    int key = kt * 32 + nt * 8 + 2 * tg + (c & 1);
                    int rr = row0 + ((c & 2) ? 8 : 0);
                    if (key > rr) s[nt][c] = -1e30f;
                }
        }

#pragma unroll
        for (int r = 0; r < 2; r++) {
            const int cb = 2 * r;
            float mx = mr[r];
#pragma unroll
            for (int nt = 0; nt < 4; nt++)
                mx = fmaxf(mx, fmaxf(s[nt][cb], s[nt][cb + 1]));
            mx = fmaxf(mx, __shfl_xor_sync(0xffffffffu, mx, 1));
            mx = fmaxf(mx, __shfl_xor_sync(0xffffffffu, mx, 2));
            float alpha = __expf(mr[r] - mx);
            float rs = 0.f;
#pragma unroll
            for (int nt = 0; nt < 4; nt++) {
                float p0 = __expf(s[nt][cb] - mx);
                float p1 = __expf(s[nt][cb + 1] - mx);
                s[nt][cb] = p0; s[nt][cb + 1] = p1;
                rs += p0 + p1;
            }
            rs += __shfl_xor_sync(0xffffffffu, rs, 1);
            rs += __shfl_xor_sync(0xffffffffu, rs, 2);
            lsum[r] = lsum[r] * alpha + rs;
            mr[r] = mx;
#pragma unroll
            for (int nt = 0; nt < 8; nt++) {
                o[nt][cb] *= alpha; o[nt][cb + 1] *= alpha;
            }
        }

#pragma unroll
        for (int nt = 0; nt < 4; nt++) {
            uint32_t ph, pl;
            split_pack(s[nt][0], s[nt][1], ph, pl);
            sPh[(warp * 16 + g) * 20 + nt * 4 + tg] = ph;
            sPl[(warp * 16 + g) * 20 + nt * 4 + tg] = pl;
            split_pack(s[nt][2], s[nt][3], ph, pl);
            sPh[(warp * 16 + g + 8) * 20 + nt * 4 + tg] = ph;
            sPl[(warp * 16 + g + 8) * 20 + nt * 4 + tg] = pl;
        }
        __syncwarp();

#pragma unroll
        for (int ks = 0; ks < 2; ks++) {
            const uint32_t ko = ks * 32;
            uint32_t ph[4], pl[4];
            ldsm4(ph, pH0 + ko);
            ldsm4(pl, pL0 + ko);
#pragma unroll
            for (int j = 0; j < 4; j++) {
                uint32_t vh[4], vl[4];
                ldsm4(vh, vH0 + ko + j * 1280);
                ldsm4(vl, vL0 + ko + j * 1280);
                mma16(o[2 * j],     ph, vh[0], vh[1]);
                mma16(o[2 * j],     pl, vh[0], vh[1]);
                mma16(o[2 * j],     ph, vl[0], vl[1]);
                mma16(o[2 * j + 1], ph, vh[2], vh[3]);
                mma16(o[2 * j + 1], pl, vh[2], vh[3]);
                mma16(o[2 * j + 1], ph, vl[2], vl[3]);
            }
        }
    }

    const int bb = bh >> 4, hh = bh & 15;
    const float inv0 = 1.f / lsum[0], inv1 = 1.f / lsum[1];
#pragma unroll
    for (int nt = 0; nt < 8; nt++) {
        int col = hh * 64 + nt * 8 + 2 * tg;
        size_t off = (size_t)(bb * NT + row0) * NC + col;
        uint32_t ph, pl;
        split_pack(o[nt][0] * inv0, o[nt][1] * inv0, ph, pl);
        *(uint32_t*)(g_xh + off) = ph;
        *(uint32_t*)(g_xl + off) = pl;
        split_pack(o[nt][2] * inv1, o[nt][3] * inv1, ph, pl);
        *(uint32_t*)(g_xh + off + 8 * NC) = ph;
        *(uint32_t*)(g_xl + off + 8 * NC) = pl;
    }
}

// ---------------- launcher --------------------------------------------------
extern "C" void kernel_launch(void* const* d_in, const int* in_sizes, int n_in,
                              void* d_out, int out_size)
{
    const float* x  = (const float*)d_in[0];
    const float* Wq = (const float*)d_in[1];
    const float* Wk = (const float*)d_in[2];
    const float* Wv = (const float*)d_in[3];
    const float* Wo = (const float*)d_in[4];
    const float* bo = (const float*)d_in[5];
    float* out = (float*)d_out;

    const int smem_flash = 19200 * 4;   // 75 KB
    cudaFuncSetAttribute(gemm_bf16_kernel<0>, cudaFuncAttributeMaxDynamicSharedMemorySize, GEMM_SMEM);
    cudaFuncSetAttribute(gemm_bf16_kernel<1>, cudaFuncAttributeMaxDynamicSharedMemorySize, GEMM_SMEM);
    cudaFuncSetAttribute(flash_attn_kernel, cudaFuncAttributeMaxDynamicSharedMemorySize, smem_flash);

    // 1) pre-split x + all weights to bf16 hi/lo (one fused launch)
    split_all_kernel<<<12288, 256>>>(x, Wq, Wk, Wv, Wo);

    // 2) QKV projection -> g_qh/ql, g_kh/kl (bf16-split), g_v (f32)
    gemm_bf16_kernel<0><<<dim3(12, 64), 256, GEMM_SMEM>>>(nullptr, nullptr);

    // 3) causal flash attention -> g_xh/g_xl (attn out, bf16-split)
    flash_attn_kernel<<<dim3(NT / 128, NB * NH), 256, smem_flash>>>();

    // 4) out projection + bias -> d_out
    gemm_bf16_kernel<1><<<dim3(4, 64), 256, GEMM_SMEM>>>(bo, out);
}

// round 14
// speedup vs baseline: 1.1779x; 1.1779x over previous
#include <cuda_runtime.h>
#include <cuda_bf16.h>
#include <cuda_fp16.h>
#include <cstdint>

#define NB 4
#define NT 2048
#define NC 1024
#define NH 16
#define NHS 64

// ---------------- scratch (static device globals) ---------------------------
__device__ __half g_vh[(size_t)NB * NH * NT * NHS];            // V, fp16-rounded
__device__ __nv_bfloat16 g_qh[(size_t)NB * NH * NT * NHS];
__device__ __nv_bfloat16 g_ql[(size_t)NB * NH * NT * NHS];
__device__ __nv_bfloat16 g_kh[(size_t)NB * NH * NT * NHS];
__device__ __nv_bfloat16 g_kl[(size_t)NB * NH * NT * NHS];
__device__ __nv_bfloat16 g_xh[(size_t)NB * NT * NC];  // x bf16-split; then attn-out fp16-split
__device__ __nv_bfloat16 g_xl[(size_t)NB * NT * NC];
__device__ __nv_bfloat16 g_wh[(size_t)3 * NC * NC];   // Wq|Wk|Wv rows concat (bf16 split)
__device__ __nv_bfloat16 g_wl[(size_t)3 * NC * NC];
__device__ __half g_woh[(size_t)NC * NC];             // Wo fp16-rounded (hi only)

// ---------------- helpers ---------------------------------------------------
__device__ __forceinline__ void mma16(float* d, const uint32_t* a, uint32_t b0, uint32_t b1) {
    asm volatile(
        "mma.sync.aligned.m16n8k16.row.col.f32.bf16.bf16.f32 "
        "{%0,%1,%2,%3}, {%4,%5,%6,%7}, {%8,%9}, {%0,%1,%2,%3};"
        : "+f"(d[0]), "+f"(d[1]), "+f"(d[2]), "+f"(d[3])
        : "r"(a[0]), "r"(a[1]), "r"(a[2]), "r"(a[3]), "r"(b0), "r"(b1));
}
__device__ __forceinline__ void mma16h(float* d, const uint32_t* a, uint32_t b0, uint32_t b1) {
    asm volatile(
        "mma.sync.aligned.m16n8k16.row.col.f32.f16.f16.f32 "
        "{%0,%1,%2,%3}, {%4,%5,%6,%7}, {%8,%9}, {%0,%1,%2,%3};"
        : "+f"(d[0]), "+f"(d[1]), "+f"(d[2]), "+f"(d[3])
        : "r"(a[0]), "r"(a[1]), "r"(a[2]), "r"(a[3]), "r"(b0), "r"(b1));
}
__device__ __forceinline__ void ldsm4(uint32_t* r, uint32_t addr) {
    asm volatile("ldmatrix.sync.aligned.m8n8.x4.shared.b16 {%0,%1,%2,%3}, [%4];"
                 : "=r"(r[0]), "=r"(r[1]), "=r"(r[2]), "=r"(r[3]) : "r"(addr));
}
__device__ __forceinline__ void split_pack(float a, float b, uint32_t& h, uint32_t& l) {
    __nv_bfloat16 ha = __float2bfloat16(a), hb = __float2bfloat16(b);
    __nv_bfloat162 th; th.x = ha; th.y = hb;
    h = *(uint32_t*)&th;
    __nv_bfloat162 tl;
    tl.x = __float2bfloat16(a - __bfloat162float(ha));
    tl.y = __float2bfloat16(b - __bfloat162float(hb));
    l = *(uint32_t*)&tl;
}
__device__ __forceinline__ void split_pack_h(float a, float b, uint32_t& h, uint32_t& l) {
    __half ha = __float2half_rn(a), hb = __float2half_rn(b);
    __half2 th; th.x = ha; th.y = hb;
    h = *(uint32_t*)&th;
    __half2 tl;
    tl.x = __float2half_rn(a - __half2float(ha));
    tl.y = __float2half_rn(b - __half2float(hb));
    l = *(uint32_t*)&tl;
}
__device__ __forceinline__ uint32_t pack_h2(float a, float b) {
    __half2 t; t.x = __float2half_rn(a); t.y = __float2half_rn(b);
    return *(uint32_t*)&t;
}
#define CPA16(dst, src) \
    asm volatile("cp.async.cg.shared.global [%0], [%1], 16;" :: "r"(dst), "l"(src))
#define CPA_COMMIT() asm volatile("cp.async.commit_group;" ::: "memory")
#define CPA_WAIT1() asm volatile("cp.async.wait_group 1;" ::: "memory")
#define CPA_WAIT0() asm volatile("cp.async.wait_group 0;" ::: "memory")

// ---------------- fused split: x + Wq/k/v (bf16 hi/lo), Wo (fp16 hi) --------
__global__ void __launch_bounds__(256) split_all_kernel(
    const float* __restrict__ x,  const float* __restrict__ Wq,
    const float* __restrict__ Wk, const float* __restrict__ Wv,
    const float* __restrict__ Wo)
{
    const size_t XN = (size_t)NB * NT * NC;   // 8M
    const size_t WN = (size_t)NC * NC;        // 1M
    size_t i = ((size_t)blockIdx.x * 256 + threadIdx.x) * 4;
    if (i >= XN + 3 * WN) {                    // Wo -> fp16 hi only
        size_t off = i - XN - 3 * WN;
        float4 v = *(const float4*)(Wo + off);
        *(uint32_t*)(g_woh + off)     = pack_h2(v.x, v.y);
        *(uint32_t*)(g_woh + off + 2) = pack_h2(v.z, v.w);
        return;
    }
    const float* src;
    __nv_bfloat16 *dh, *dl;
    size_t off;
    if (i < XN)               { src = x;  dh = g_xh;          dl = g_xl;          off = i; }
    else if (i < XN + WN)     { src = Wq; dh = g_wh;          dl = g_wl;          off = i - XN; }
    else if (i < XN + 2 * WN) { src = Wk; dh = g_wh + WN;     dl = g_wl + WN;     off = i - XN - WN; }
    else                      { src = Wv; dh = g_wh + 2 * WN; dl = g_wl + 2 * WN; off = i - XN - 2 * WN; }
    float4 v = *(const float4*)(src + off);
    uint32_t h0, l0, h1, l1;
    split_pack(v.x, v.y, h0, l0);
    split_pack(v.z, v.w, h1, l1);
    *(uint32_t*)(dh + off) = h0; *(uint32_t*)(dh + off + 2) = h1;
    *(uint32_t*)(dl + off) = l0; *(uint32_t*)(dl + off + 2) = l1;
}

// ---------------- GEMM (R9 config: 128x128 tile, 2-stage, 2 CTA/SM) ---------
// MODE 0: 3xBF16, A=x split, B=Wqkv split; scatter q/k (bf16 split) + v (fp16).
// MODE 1: 2xFP16, A=attn fp16 pair (exact), B=Wo fp16 (rounded); Out=C+bias.
static constexpr int G_STG = 10240;  // u32 per stage (4 arrays x 128 x 20)
static constexpr int GEMM_SMEM = 2 * G_STG * 4;  // 81920 B

template <int MODE>
__global__ void __launch_bounds__(256, 2) gemm_bf16_kernel(
    const float* __restrict__ bias, float* __restrict__ Out)
{
    extern __shared__ uint32_t su[];

    const int tid = threadIdx.x;
    const int warp = tid >> 5, lane = tid & 31;
    const int g = lane >> 2, tg = lane & 3;
    const int wm = warp >> 2, wn = warp & 3;      // 2x4 warps, warp tile 64x32
    const int m0 = blockIdx.y * 128;
    const int n0 = blockIdx.x * 128;

    const __nv_bfloat16* Ah = g_xh;
    const __nv_bfloat16* Al = g_xl;
    const __nv_bfloat16* Bh = (MODE == 0) ? g_wh : (const __nv_bfloat16*)g_woh;
    const __nv_bfloat16* Bl = (MODE == 0) ? g_wl : (const __nv_bfloat16*)g_woh;

    float acc[4][4][4];
#pragma unroll
    for (int a = 0; a < 4; a++)
#pragma unroll
        for (int b = 0; b < 4; b++)
#pragma unroll
            for (int c = 0; c < 4; c++) acc[a][b][c] = 0.f;

    const int lr = tid >> 1;            // 0..127 (tile row)
    const int lc = (tid & 1) * 8;       // u32 col base 0 or 8
    const __nv_bfloat16* pA_h = Ah + (size_t)(m0 + lr) * NC + lc * 2;
    const __nv_bfloat16* pA_l = Al + (size_t)(m0 + lr) * NC + lc * 2;
    const __nv_bfloat16* pB_h = Bh + (size_t)(n0 + lr) * NC + lc * 2;
    const __nv_bfloat16* pB_l = Bl + (size_t)(n0 + lr) * NC + lc * 2;
    const uint32_t sb = (uint32_t)__cvta_generic_to_shared(su);
    const uint32_t sdst = sb + (lr * 20 + lc) * 4;

    // ldmatrix lane addressing
    const int lm = lane & 7, sel = lane >> 3;
    const int rowA = lm + ((sel & 1) << 3), colA = (sel & 2) << 1;
    const int rowB = lm + ((sel & 2) << 2), colB = (sel & 1) << 2;
    const uint32_t aH0 = sb + ((wm * 64 + rowA) * 20 + colA) * 4;
    const uint32_t aL0 = aH0 + 2560 * 4;
    const uint32_t bH0 = sb + 5120 * 4 + ((wn * 32 + rowB) * 20 + colB) * 4;
    const uint32_t bL0 = bH0 + 2560 * 4;

#define G_LOAD(S, KT)                                                          \
    {                                                                          \
        uint32_t d0 = sdst + (S) * (G_STG * 4);                                \
        CPA16(d0,                 pA_h + (KT));                                \
        CPA16(d0 + 16,            pA_h + (KT) + 8);                            \
        CPA16(d0 + 2560 * 4,      pA_l + (KT));                                \
        CPA16(d0 + 2560 * 4 + 16, pA_l + (KT) + 8);                            \
        CPA16(d0 + 5120 * 4,      pB_h + (KT));                                \
        CPA16(d0 + 5120 * 4 + 16, pB_h + (KT) + 8);                            \
        if (MODE == 0) {                                                       \
            CPA16(d0 + 7680 * 4,      pB_l + (KT));                            \
            CPA16(d0 + 7680 * 4 + 16, pB_l + (KT) + 8);                        \
        }                                                                      \
        CPA_COMMIT();                                                          \
    }

    G_LOAD(0, 0);

    for (int c = 0; c < 32; c++) {
        if (c < 31) { G_LOAD((c + 1) & 1, (c + 1) * 32); CPA_WAIT1(); }
        else        { CPA_WAIT0(); }
        __syncthreads();
        const uint32_t stg = (c & 1) * (G_STG * 4);

#pragma unroll
        for (int ks = 0; ks < 2; ks++) {
            const uint32_t ko = stg + ks * 32;
            uint32_t ah[4][4], al[4][4];
#pragma unroll
            for (int mt = 0; mt < 4; mt++) {
                ldsm4(ah[mt], aH0 + ko + mt * 1280);
                ldsm4(al[mt], aL0 + ko + mt * 1280);
            }
#pragma unroll
            for (int j = 0; j < 2; j++) {
                uint32_t bh[4];
                ldsm4(bh, bH0 + ko + j * 1280);
                if (MODE == 0) {
                    uint32_t bl[4];
                    ldsm4(bl, bL0 + ko + j * 1280);
#pragma unroll
                    for (int mt = 0; mt < 4; mt++) {
                        mma16(acc[mt][2 * j],     ah[mt], bh[0], bh[1]);
                        mma16(acc[mt][2 * j],     al[mt], bh[0], bh[1]);
                        mma16(acc[mt][2 * j],     ah[mt], bl[0], bl[1]);
                        mma16(acc[mt][2 * j + 1], ah[mt], bh[2], bh[3]);
                        mma16(acc[mt][2 * j + 1], al[mt], bh[2], bh[3]);
                        mma16(acc[mt][2 * j + 1], ah[mt], bl[2], bl[3]);
                    }
                } else {
#pragma unroll
                    for (int mt = 0; mt < 4; mt++) {
                        mma16h(acc[mt][2 * j],     ah[mt], bh[0], bh[1]);
                        mma16h(acc[mt][2 * j],     al[mt], bh[0], bh[1]);
                        mma16h(acc[mt][2 * j + 1], ah[mt], bh[2], bh[3]);
                        mma16h(acc[mt][2 * j + 1], al[mt], bh[2], bh[3]);
                    }
                }
            }
        }
        __syncthreads();
    }

    // epilogue
#pragma unroll
    for (int mt = 0; mt < 4; mt++) {
        int row = m0 + wm * 64 + mt * 16 + g;
#pragma unroll
        for (int nt = 0; nt < 4; nt++) {
            int colg = blockIdx.x * 128 + wn * 32 + nt * 8 + 2 * tg;
            if (MODE == 0) {
                int sl = colg >> 10, cc = colg & 1023;
                int h = cc >> 6, d = cc & 63;
                int b = row >> 11, t = row & (NT - 1);
                size_t off = (((size_t)(b * NH + h) * NT) + t) * NHS + d;
                if (sl == 2) {
                    *(uint32_t*)(g_vh + off) = pack_h2(acc[mt][nt][0], acc[mt][nt][1]);
                    *(uint32_t*)(g_vh + off + 8 * NHS) = pack_h2(acc[mt][nt][2], acc[mt][nt][3]);
                } else {
                    float sc = (sl == 0) ? 8.f : 1.f;   // pre-scale Q by sqrt(HS)
                    __nv_bfloat16* dh = (sl == 0) ? g_qh : g_kh;
                    __nv_bfloat16* dl = (sl == 0) ? g_ql : g_kl;
                    uint32_t ph, pl;
                    split_pack(acc[mt][nt][0] * sc, acc[mt][nt][1] * sc, ph, pl);
                    *(uint32_t*)(dh + off) = ph;
                    *(uint32_t*)(dl + off) = pl;
                    split_pack(acc[mt][nt][2] * sc, acc[mt][nt][3] * sc, ph, pl);
                    *(uint32_t*)(dh + off + 8 * NHS) = ph;
                    *(uint32_t*)(dl + off + 8 * NHS) = pl;
                }
            } else {
                float2 bv = *(const float2*)(bias + colg);
                *(float2*)(Out + (size_t)row * NC + colg) =
                    make_float2(acc[mt][nt][0] + bv.x, acc[mt][nt][1] + bv.y);
                *(float2*)(Out + (size_t)(row + 8) * NC + colg) =
                    make_float2(acc[mt][nt][2] + bv.x, acc[mt][nt][3] + bv.y);
            }
        }
    }
}

// ---------------- flash attention: S 3xBF16, PV 2xFP16 ----------------------
__global__ void __launch_bounds__(256, 2) flash_attn_kernel()
{
    extern __shared__ uint32_t su[];
    uint32_t* sQh = su;            // 128*36
    uint32_t* sQl = su + 4608;
    uint32_t* sKh = su + 9216;     // 32*36
    uint32_t* sKl = su + 10368;
    uint32_t* sVh = su + 11520;    // 64*20 (fp16 h2 words)
    uint32_t* sPh = su + 14080;    // 128*20 (fp16 pair)
    uint32_t* sPl = su + 16640;    // total 19200 u32

    const int tid = threadIdx.x;
    const int warp = tid >> 5, lane = tid & 31;
    const int g = lane >> 2, tg = lane & 3;
    const int qi = (int)gridDim.x - 1 - (int)blockIdx.x;   // longest first
    const int bh = blockIdx.y;

    const size_t base = (size_t)bh * NT * NHS;
    const __nv_bfloat16* Qhg = g_qh + base + (size_t)qi * 128 * NHS;
    const __nv_bfloat16* Qlg = g_ql + base + (size_t)qi * 128 * NHS;
    const __nv_bfloat16* Khg = g_kh + base;
    const __nv_bfloat16* Klg = g_kl + base;
    const __half* Vg = g_vh + base;

    const uint32_t sb = (uint32_t)__cvta_generic_to_shared(su);
    const int lm = lane & 7, sel = lane >> 3;
    const int rowA = lm + ((sel & 1) << 3), colA = (sel & 2) << 1;
    const int rowB = lm + ((sel & 2) << 2), colB = (sel & 1) << 2;
    const uint32_t qH0 = sb + ((warp * 16 + rowA) * 36 + colA) * 4;
    const uint32_t qL0 = qH0 + 4608 * 4;
    const uint32_t kH0 = sb + 9216 * 4 + (rowB * 36 + colB) * 4;
    const uint32_t kL0 = kH0 + 1152 * 4;
    const uint32_t vH0 = sb + 11520 * 4 + (rowB * 20 + colB) * 4;
    const uint32_t pH0 = sb + 14080 * 4 + ((warp * 16 + rowA) * 20 + colA) * 4;
    const uint32_t pL0 = pH0 + 2560 * 4;

    {
        int r = tid >> 1, cc = (tid & 1) * 16;
#pragma unroll
        for (int j = 0; j < 4; j++) {
            int eo = (cc + 4 * j) * 2;
            *(uint4*)&sQh[r * 36 + cc + 4 * j] = *(const uint4*)(Qhg + r * NHS + eo);
            *(uint4*)&sQl[r * 36 + cc + 4 * j] = *(const uint4*)(Qlg + r * NHS + eo);
        }
    }

    float o[8][4];
#pragma unroll
    for (int i = 0; i < 8; i++)
#pragma unroll
        for (int j = 0; j < 4; j++) o[i][j] = 0.f;
    float mr[2] = {-1e30f, -1e30f}, lsum[2] = {0.f, 0.f};

    const int row0 = qi * 128 + warp * 16 + g;
    const int nkt = 4 * qi + 4;

    const int kr = tid >> 3, kc = (tid & 7) * 4;
    const int vd = tid & 63, vq = tid >> 6;
    uint4 rkh, rkl;
    __half rv0[4], rv1[4];
#define LD_KV(KT)                                                                  \
    {                                                                              \
        rkh = *(const uint4*)(Khg + (size_t)((KT) * 32 + kr) * NHS + kc * 2);      \
        rkl = *(const uint4*)(Klg + (size_t)((KT) * 32 + kr) * NHS + kc * 2);      \
        _Pragma("unroll") for (int i = 0; i < 4; i++) {                            \
            int kp = vq * 4 + i;                                                   \
            rv0[i] = Vg[(size_t)((KT) * 32 + 2 * kp) * NHS + vd];                  \
            rv1[i] = Vg[(size_t)((KT) * 32 + 2 * kp + 1) * NHS + vd];              \
        }                                                                          \
    }
    LD_KV(0);

    for (int kt = 0; kt < nkt; kt++) {
        __syncthreads();
        *(uint4*)&sKh[kr * 36 + kc] = rkh;
        *(uint4*)&sKl[kr * 36 + kc] = rkl;
        {
            uint4 vh4;
            __half2 t;
            t.x = rv0[0]; t.y = rv1[0]; vh4.x = *(uint32_t*)&t;
            t.x = rv0[1]; t.y = rv1[1]; vh4.y = *(uint32_t*)&t;
            t.x = rv0[2]; t.y = rv1[2]; vh4.z = *(uint32_t*)&t;
            t.x = rv0[3]; t.y = rv1[3]; vh4.w = *(uint32_t*)&t;
            *(uint4*)&sVh[vd * 20 + vq * 4] = vh4;
        }
        __syncthreads();
        if (kt + 1 < nkt) LD_KV(kt + 1);

        if (kt * 32 > qi * 128 + warp * 16 + 15) continue;

        // S = Q K^T (16x32 per warp), 3xBF16
        float s[4][4];
#pragma unroll
        for (int i = 0; i < 4; i++)
#pragma unroll
            for (int j = 0; j < 4; j++) s[i][j] = 0.f;

#pragma unroll
        for (int ks = 0; ks < 4; ks++) {
            const uint32_t ko = ks * 32;
            uint32_t qh[4], ql[4];
            ldsm4(qh, qH0 + ko);
            ldsm4(ql, qL0 + ko);
#pragma unroll
            for (int j = 0; j < 2; j++) {
                uint32_t kh[4], kl[4];
                ldsm4(kh, kH0 + ko + j * 2304);
                ldsm4(kl, kL0 + ko + j * 2304);
                mma16(s[2 * j],     qh, kh[0], kh[1]);
                mma16(s[2 * j],     ql, kh[0], kh[1]);
                mma16(s[2 * j],     qh, kl[0], kl[1]);
                mma16(s[2 * j + 1], qh, kh[2], kh[3]);
                mma16(s[2 * j + 1], ql, kh[2], kh[3]);
                mma16(s[2 * j + 1], qh, kl[2], kl[3]);
            }
        }

        if (kt * 32 + 31 > qi * 128 + warp * 16) {
#pragma unroll
            for (int nt = 0; nt < 4; nt++)
#pragma unroll
                for (int c = 0; c < 4; c++) {
                    int key = kt * 32 + nt * 8 + 2 * tg + (c & 1);
                    int rr = row0 + ((c & 2) ? 8 : 0);
                    if (key > rr) s[nt][c] = -1e30f;
                }
        }

#pragma unroll
        for (int r = 0; r < 2; r++) {
            const int cb = 2 * r;
            float mx = mr[r];
#pragma unroll
            for (int nt = 0; nt < 4; nt++)
                mx = fmaxf(mx, fmaxf(s[nt][cb], s[nt][cb + 1]));
            mx = fmaxf(mx, __shfl_xor_sync(0xffffffffu, mx, 1));
            mx = fmaxf(mx, __shfl_xor_sync(0xffffffffu, mx, 2));
            float alpha = __expf(mr[r] - mx);
            float rs = 0.f;
#pragma unroll
            for (int nt = 0; nt < 4; nt++) {
                float p0 = __expf(s[nt][cb] - mx);
                float p1 = __expf(s[nt][cb + 1] - mx);
                s[nt][cb] = p0; s[nt][cb + 1] = p1;
                rs += p0 + p1;
            }
            rs += __shfl_xor_sync(0xffffffffu, rs, 1);
            rs += __shfl_xor_sync(0xffffffffu, rs, 2);
            lsum[r] = lsum[r] * alpha + rs;
            mr[r] = mx;
#pragma unroll
            for (int nt = 0; nt < 8; nt++) {
                o[nt][cb] *= alpha; o[nt][cb + 1] *= alpha;
            }
        }

        // stage P as fp16 pair (warp-private rows)
#pragma unroll
        for (int nt = 0; nt < 4; nt++) {
            uint32_t ph, pl;
            split_pack_h(s[nt][0], s[nt][1], ph, pl);
            sPh[(warp * 16 + g) * 20 + nt * 4 + tg] = ph;
            sPl[(warp * 16 + g) * 20 + nt * 4 + tg] = pl;
            split_pack_h(s[nt][2], s[nt][3], ph, pl);
            sPh[(warp * 16 + g + 8) * 20 + nt * 4 + tg] = ph;
            sPl[(warp * 16 + g + 8) * 20 + nt * 4 + tg] = pl;
        }
        __syncwarp();

        // O += P V : 2xFP16 (P exact pair, V rounded)
#pragma unroll
        for (int ks = 0; ks < 2; ks++) {
            const uint32_t ko = ks * 32;
            uint32_t ph[4], pl[4];
            ldsm4(ph, pH0 + ko);
            ldsm4(pl, pL0 + ko);
#pragma unroll
            for (int j = 0; j < 4; j++) {
                uint32_t vh[4];
                ldsm4(vh, vH0 + ko + j * 1280);
                mma16h(o[2 * j],     ph, vh[0], vh[1]);
                mma16h(o[2 * j],     pl, vh[0], vh[1]);
                mma16h(o[2 * j + 1], ph, vh[2], vh[3]);
                mma16h(o[2 * j + 1], pl, vh[2], vh[3]);
            }
        }
    }

    // normalize + write attn-out as fp16 pair into g_xh/g_xl [B,T,C]
    const int bb = bh >> 4, hh = bh & 15;
    const float inv0 = 1.f / lsum[0], inv1 = 1.f / lsum[1];
#pragma unroll
    for (int nt = 0; nt < 8; nt++) {
        int col = hh * 64 + nt * 8 + 2 * tg;
        size_t off = (size_t)(bb * NT + row0) * NC + col;
        uint32_t ph, pl;
        split_pack_h(o[nt][0] * inv0, o[nt][1] * inv0, ph, pl);
        *(uint32_t*)(g_xh + off) = ph;
        *(uint32_t*)(g_xl + off) = pl;
        split_pack_h(o[nt][2] * inv1, o[nt][3] * inv1, ph, pl);
        *(uint32_t*)(g_xh + off + 8 * NC) = ph;
        *(uint32_t*)(g_xl + off + 8 * NC) = pl;
    }
}

// ---------------- launcher --------------------------------------------------
extern "C" void kernel_launch(void* const* d_in, const int* in_sizes, int n_in,
                              void* d_out, int out_size)
{
    const float* x  = (const float*)d_in[0];
    const float* Wq = (const float*)d_in[1];
    const float* Wk = (const float*)d_in[2];
    const float* Wv = (const float*)d_in[3];
    const float* Wo = (const float*)d_in[4];
    const float* bo = (const float*)d_in[5];
    float* out = (float*)d_out;

    const int smem_flash = 19200 * 4;   // 75 KB
    cudaFuncSetAttribute(gemm_bf16_kernel<0>, cudaFuncAttributeMaxDynamicSharedMemorySize, GEMM_SMEM);
    cudaFuncSetAttribute(gemm_bf16_kernel<1>, cudaFuncAttributeMaxDynamicSharedMemorySize, GEMM_SMEM);
    cudaFuncSetAttribute(flash_attn_kernel, cudaFuncAttributeMaxDynamicSharedMemorySize, smem_flash);

    // 1) pre-split x + weights (one fused launch)
    split_all_kernel<<<12288, 256>>>(x, Wq, Wk, Wv, Wo);

    // 2) QKV projection -> g_qh/ql, g_kh/kl (bf16-split), g_vh (fp16)
    gemm_bf16_kernel<0><<<dim3(24, 64), 256, GEMM_SMEM>>>(nullptr, nullptr);

    // 3) causal flash attention -> g_xh/g_xl (attn out, fp16 pair)
    flash_attn_kernel<<<dim3(NT / 128, NB * NH), 256, smem_flash>>>();

    // 4) out projection (2xFP16) + bias -> d_out
    gemm_bf16_kernel<1><<<dim3(8, 64), 256, GEMM_SMEM>>>(bo, out);
}

// round 15
// speedup vs baseline: 1.3658x; 1.1595x over previous
#include <cuda_runtime.h>
#include <cuda_bf16.h>
#include <cuda_fp16.h>
#include <cstdint>

#define NB 4
#define NT 2048
#define NC 1024
#define NH 16
#define NHS 64

// ---------------- scratch (static device globals) ---------------------------
__device__ __half g_vh[(size_t)NB * NH * NT * NHS];   // V, fp16-rounded
__device__ __nv_bfloat16 g_qh[(size_t)NB * NH * NT * NHS];
__device__ __nv_bfloat16 g_ql[(size_t)NB * NH * NT * NHS];
__device__ __nv_bfloat16 g_kh[(size_t)NB * NH * NT * NHS];
__device__ __nv_bfloat16 g_kl[(size_t)NB * NH * NT * NHS];
__device__ __nv_bfloat16 g_xh[(size_t)NB * NT * NC];  // x bf16 hi/lo (QK path)
__device__ __nv_bfloat16 g_xl[(size_t)NB * NT * NC];
__device__ __half g_xfh[(size_t)NB * NT * NC];        // x fp16 hi/lo (V path); then attn-out fp16
__device__ __half g_xfl[(size_t)NB * NT * NC];
__device__ __nv_bfloat16 g_wh[(size_t)2 * NC * NC];   // Wq|Wk rows (bf16 split)
__device__ __nv_bfloat16 g_wl[(size_t)2 * NC * NC];
__device__ __half g_wvh[(size_t)NC * NC];             // Wv fp16-rounded
__device__ __half g_woh[(size_t)NC * NC];             // Wo fp16-rounded

// ---------------- helpers ---------------------------------------------------
__device__ __forceinline__ void mma16(float* d, const uint32_t* a, uint32_t b0, uint32_t b1) {
    asm volatile(
        "mma.sync.aligned.m16n8k16.row.col.f32.bf16.bf16.f32 "
        "{%0,%1,%2,%3}, {%4,%5,%6,%7}, {%8,%9}, {%0,%1,%2,%3};"
        : "+f"(d[0]), "+f"(d[1]), "+f"(d[2]), "+f"(d[3])
        : "r"(a[0]), "r"(a[1]), "r"(a[2]), "r"(a[3]), "r"(b0), "r"(b1));
}
__device__ __forceinline__ void mma16h(float* d, const uint32_t* a, uint32_t b0, uint32_t b1) {
    asm volatile(
        "mma.sync.aligned.m16n8k16.row.col.f32.f16.f16.f32 "
        "{%0,%1,%2,%3}, {%4,%5,%6,%7}, {%8,%9}, {%0,%1,%2,%3};"
        : "+f"(d[0]), "+f"(d[1]), "+f"(d[2]), "+f"(d[3])
        : "r"(a[0]), "r"(a[1]), "r"(a[2]), "r"(a[3]), "r"(b0), "r"(b1));
}
__device__ __forceinline__ void ldsm4(uint32_t* r, uint32_t addr) {
    asm volatile("ldmatrix.sync.aligned.m8n8.x4.shared.b16 {%0,%1,%2,%3}, [%4];"
                 : "=r"(r[0]), "=r"(r[1]), "=r"(r[2]), "=r"(r[3]) : "r"(addr));
}
__device__ __forceinline__ void split_pack(float a, float b, uint32_t& h, uint32_t& l) {
    __nv_bfloat16 ha = __float2bfloat16(a), hb = __float2bfloat16(b);
    __nv_bfloat162 th; th.x = ha; th.y = hb;
    h = *(uint32_t*)&th;
    __nv_bfloat162 tl;
    tl.x = __float2bfloat16(a - __bfloat162float(ha));
    tl.y = __float2bfloat16(b - __bfloat162float(hb));
    l = *(uint32_t*)&tl;
}
__device__ __forceinline__ void split_pack_h(float a, float b, uint32_t& h, uint32_t& l) {
    __half ha = __float2half_rn(a), hb = __float2half_rn(b);
    __half2 th; th.x = ha; th.y = hb;
    h = *(uint32_t*)&th;
    __half2 tl;
    tl.x = __float2half_rn(a - __half2float(ha));
    tl.y = __float2half_rn(b - __half2float(hb));
    l = *(uint32_t*)&tl;
}
__device__ __forceinline__ uint32_t pack_h2(float a, float b) {
    __half2 t; t.x = __float2half_rn(a); t.y = __float2half_rn(b);
    return *(uint32_t*)&t;
}
#define CPA16(dst, src) \
    asm volatile("cp.async.cg.shared.global [%0], [%1], 16;" :: "r"(dst), "l"(src))
#define CPA_COMMIT() asm volatile("cp.async.commit_group;" ::: "memory")
#define CPA_WAIT1() asm volatile("cp.async.wait_group 1;" ::: "memory")
#define CPA_WAIT0() asm volatile("cp.async.wait_group 0;" ::: "memory")

// ---------------- fused split ------------------------------------------------
// x -> bf16 hi/lo AND fp16 hi/lo; Wq,Wk -> bf16 hi/lo; Wv,Wo -> fp16 single.
__global__ void __launch_bounds__(256) split_all_kernel(
    const float* __restrict__ x,  const float* __restrict__ Wq,
    const float* __restrict__ Wk, const float* __restrict__ Wv,
    const float* __restrict__ Wo)
{
    const size_t XN = (size_t)NB * NT * NC;   // 8M
    const size_t WN = (size_t)NC * NC;        // 1M
    size_t i = ((size_t)blockIdx.x * 256 + threadIdx.x) * 4;
    if (i < XN) {
        float4 v = *(const float4*)(x + i);
        uint32_t h0, l0, h1, l1;
        split_pack(v.x, v.y, h0, l0); split_pack(v.z, v.w, h1, l1);
        *(uint32_t*)(g_xh + i) = h0; *(uint32_t*)(g_xh + i + 2) = h1;
        *(uint32_t*)(g_xl + i) = l0; *(uint32_t*)(g_xl + i + 2) = l1;
        split_pack_h(v.x, v.y, h0, l0); split_pack_h(v.z, v.w, h1, l1);
        *(uint32_t*)(g_xfh + i) = h0; *(uint32_t*)(g_xfh + i + 2) = h1;
        *(uint32_t*)(g_xfl + i) = l0; *(uint32_t*)(g_xfl + i + 2) = l1;
    } else if (i < XN + 2 * WN) {
        const float* src = (i < XN + WN) ? Wq : Wk;
        size_t off = (i < XN + WN) ? (i - XN) : (i - XN - WN);
        size_t dsto = (i < XN + WN) ? off : off + WN;
        float4 v = *(const float4*)(src + off);
        uint32_t h0, l0, h1, l1;
        split_pack(v.x, v.y, h0, l0); split_pack(v.z, v.w, h1, l1);
        *(uint32_t*)(g_wh + dsto) = h0; *(uint32_t*)(g_wh + dsto + 2) = h1;
        *(uint32_t*)(g_wl + dsto) = l0; *(uint32_t*)(g_wl + dsto + 2) = l1;
    } else {
        const float* src = (i < XN + 3 * WN) ? Wv : Wo;
        __half* dst = (i < XN + 3 * WN) ? g_wvh : g_woh;
        size_t off = (i < XN + 3 * WN) ? (i - XN - 2 * WN) : (i - XN - 3 * WN);
        float4 v = *(const float4*)(src + off);
        *(uint32_t*)(dst + off)     = pack_h2(v.x, v.y);
        *(uint32_t*)(dst + off + 2) = pack_h2(v.z, v.w);
    }
}

// ---------------- GEMM (128x128 tile, 2-stage cp.async, 2 CTA/SM) -----------
// MODE 0: QK, 3xBF16 (x bf16 pair x Wqk bf16 pair); scatter q (x8) / k, bf16 split.
// MODE 2: V,  2xFP16 (x fp16 pair exact x Wv fp16 rounded); -> g_vh fp16.
// MODE 1: out-proj, 1xFP16 (attn fp16 x Wo fp16) + bias -> Out f32.
static constexpr int G_STG = 10240;  // u32 per stage
static constexpr int GEMM_SMEM = 2 * G_STG * 4;  // 81920 B

template <int MODE>
__global__ void __launch_bounds__(256, 2) gemm_bf16_kernel(
    const float* __restrict__ bias, float* __restrict__ Out)
{
    extern __shared__ uint32_t su[];

    const int tid = threadIdx.x;
    const int warp = tid >> 5, lane = tid & 31;
    const int g = lane >> 2, tg = lane & 3;
    const int wm = warp >> 2, wn = warp & 3;      // 2x4 warps, warp tile 64x32
    const int m0 = blockIdx.y * 128;
    const int n0 = blockIdx.x * 128;

    const __nv_bfloat16 *Ah, *Al = nullptr, *Bh, *Bl = nullptr;
    if (MODE == 0) { Ah = g_xh; Al = g_xl; Bh = g_wh; Bl = g_wl; }
    else if (MODE == 2) {
        Ah = (const __nv_bfloat16*)g_xfh; Al = (const __nv_bfloat16*)g_xfl;
        Bh = (const __nv_bfloat16*)g_wvh;
    } else {
        Ah = (const __nv_bfloat16*)g_xfh;
        Bh = (const __nv_bfloat16*)g_woh;
    }

    float acc[4][4][4];
#pragma unroll
    for (int a = 0; a < 4; a++)
#pragma unroll
        for (int b = 0; b < 4; b++)
#pragma unroll
            for (int c = 0; c < 4; c++) acc[a][b][c] = 0.f;

    const int lr = tid >> 1;            // 0..127 (tile row)
    const int lc = (tid & 1) * 8;       // u32 col base 0 or 8
    const __nv_bfloat16* pA_h = Ah + (size_t)(m0 + lr) * NC + lc * 2;
    const __nv_bfloat16* pA_l = (MODE != 1) ? Al + (size_t)(m0 + lr) * NC + lc * 2 : nullptr;
    const __nv_bfloat16* pB_h = Bh + (size_t)(n0 + lr) * NC + lc * 2;
    const __nv_bfloat16* pB_l = (MODE == 0) ? Bl + (size_t)(n0 + lr) * NC + lc * 2 : nullptr;
    const uint32_t sb = (uint32_t)__cvta_generic_to_shared(su);
    const uint32_t sdst = sb + (lr * 20 + lc) * 4;

    // ldmatrix lane addressing
    const int lm = lane & 7, sel = lane >> 3;
    const int rowA = lm + ((sel & 1) << 3), colA = (sel & 2) << 1;
    const int rowB = lm + ((sel & 2) << 2), colB = (sel & 1) << 2;
    const uint32_t aH0 = sb + ((wm * 64 + rowA) * 20 + colA) * 4;
    const uint32_t aL0 = aH0 + 2560 * 4;
    const uint32_t bH0 = sb + 5120 * 4 + ((wn * 32 + rowB) * 20 + colB) * 4;
    const uint32_t bL0 = bH0 + 2560 * 4;

#define G_LOAD(S, KT)                                                          \
    {                                                                          \
        uint32_t d0 = sdst + (S) * (G_STG * 4);                                \
        CPA16(d0,                 pA_h + (KT));                                \
        CPA16(d0 + 16,            pA_h + (KT) + 8);                            \
        if (MODE != 1) {                                                       \
            CPA16(d0 + 2560 * 4,      pA_l + (KT));                            \
            CPA16(d0 + 2560 * 4 + 16, pA_l + (KT) + 8);                        \
        }                                                                      \
        CPA16(d0 + 5120 * 4,      pB_h + (KT));                                \
        CPA16(d0 + 5120 * 4 + 16, pB_h + (KT) + 8);                            \
        if (MODE == 0) {                                                       \
            CPA16(d0 + 7680 * 4,      pB_l + (KT));                            \
            CPA16(d0 + 7680 * 4 + 16, pB_l + (KT) + 8);                        \
        }                                                                      \
        CPA_COMMIT();                                                          \
    }

    G_LOAD(0, 0);

    for (int c = 0; c < 32; c++) {
        if (c < 31) { G_LOAD((c + 1) & 1, (c + 1) * 32); CPA_WAIT1(); }
        else        { CPA_WAIT0(); }
        __syncthreads();
        const uint32_t stg = (c & 1) * (G_STG * 4);

#pragma unroll
        for (int ks = 0; ks < 2; ks++) {
            const uint32_t ko = stg + ks * 32;
            uint32_t ah[4][4], al[4][4];
#pragma unroll
            for (int mt = 0; mt < 4; mt++) {
                ldsm4(ah[mt], aH0 + ko + mt * 1280);
                if (MODE != 1) ldsm4(al[mt], aL0 + ko + mt * 1280);
            }
#pragma unroll
            for (int j = 0; j < 2; j++) {
                uint32_t bh[4];
                ldsm4(bh, bH0 + ko + j * 1280);
                if (MODE == 0) {
                    uint32_t bl[4];
                    ldsm4(bl, bL0 + ko + j * 1280);
#pragma unroll
                    for (int mt = 0; mt < 4; mt++) {
                        mma16(acc[mt][2 * j],     ah[mt], bh[0], bh[1]);
                        mma16(acc[mt][2 * j],     al[mt], bh[0], bh[1]);
                        mma16(acc[mt][2 * j],     ah[mt], bl[0], bl[1]);
                        mma16(acc[mt][2 * j + 1], ah[mt], bh[2], bh[3]);
                        mma16(acc[mt][2 * j + 1], al[mt], bh[2], bh[3]);
                        mma16(acc[mt][2 * j + 1], ah[mt], bl[2], bl[3]);
                    }
                } else if (MODE == 2) {
#pragma unroll
                    for (int mt = 0; mt < 4; mt++) {
                        mma16h(acc[mt][2 * j],     ah[mt], bh[0], bh[1]);
                        mma16h(acc[mt][2 * j],     al[mt], bh[0], bh[1]);
                        mma16h(acc[mt][2 * j + 1], ah[mt], bh[2], bh[3]);
                        mma16h(acc[mt][2 * j + 1], al[mt], bh[2], bh[3]);
                    }
                } else {
#pragma unroll
                    for (int mt = 0; mt < 4; mt++) {
                        mma16h(acc[mt][2 * j],     ah[mt], bh[0], bh[1]);
                        mma16h(acc[mt][2 * j + 1], ah[mt], bh[2], bh[3]);
                    }
                }
            }
        }
        __syncthreads();
    }

    // epilogue
#pragma unroll
    for (int mt = 0; mt < 4; mt++) {
        int row = m0 + wm * 64 + mt * 16 + g;
#pragma unroll
        for (int nt = 0; nt < 4; nt++) {
            int colg = n0 + wn * 32 + nt * 8 + 2 * tg;
            int b = row >> 11, t = row & (NT - 1);
            if (MODE == 0) {
                int sl = colg >> 10, cc = colg & 1023;
                int h = cc >> 6, d = cc & 63;
                size_t off = (((size_t)(b * NH + h) * NT) + t) * NHS + d;
                float sc = (sl == 0) ? 8.f : 1.f;   // pre-scale Q by sqrt(HS)
                __nv_bfloat16* dh = (sl == 0) ? g_qh : g_kh;
                __nv_bfloat16* dl = (sl == 0) ? g_ql : g_kl;
                uint32_t ph, pl;
                split_pack(acc[mt][nt][0] * sc, acc[mt][nt][1] * sc, ph, pl);
                *(uint32_t*)(dh + off) = ph;
                *(uint32_t*)(dl + off) = pl;
                split_pack(acc[mt][nt][2] * sc, acc[mt][nt][3] * sc, ph, pl);
                *(uint32_t*)(dh + off + 8 * NHS) = ph;
                *(uint32_t*)(dl + off + 8 * NHS) = pl;
            } else if (MODE == 2) {
                int h = colg >> 6, d = colg & 63;
                size_t off = (((size_t)(b * NH + h) * NT) + t) * NHS + d;
                *(uint32_t*)(g_vh + off) = pack_h2(acc[mt][nt][0], acc[mt][nt][1]);
                *(uint32_t*)(g_vh + off + 8 * NHS) = pack_h2(acc[mt][nt][2], acc[mt][nt][3]);
            } else {
                float2 bv = *(const float2*)(bias + colg);
                *(float2*)(Out + (size_t)row * NC + colg) =
                    make_float2(acc[mt][nt][0] + bv.x, acc[mt][nt][1] + bv.y);
                *(float2*)(Out + (size_t)(row + 8) * NC + colg) =
                    make_float2(acc[mt][nt][2] + bv.x, acc[mt][nt][3] + bv.y);
            }
        }
    }
}

// ---------------- flash attention: S 3xBF16, PV 1xFP16 ----------------------
static constexpr int FLASH_SMEM = 15360 * 4;  // 61440 B

__global__ void __launch_bounds__(256, 2) flash_attn_kernel()
{
    extern __shared__ uint32_t su[];
    uint32_t* sQh = su;            // 128*36 = 4608
    uint32_t* sQl = su + 4608;
    uint32_t* sKh = su + 9216;     // 32*36 = 1152
    uint32_t* sKl = su + 10368;
    uint32_t* sVh = su + 11520;    // 64*20 = 1280 (fp16 h2)
    uint32_t* sPh = su + 12800;    // 128*20 = 2560 (fp16 rounded)

    const int tid = threadIdx.x;
    const int warp = tid >> 5, lane = tid & 31;
    const int g = lane >> 2, tg = lane & 3;
    const int qi = (int)gridDim.x - 1 - (int)blockIdx.x;   // longest first
    const int bh = blockIdx.y;

    const size_t base = (size_t)bh * NT * NHS;
    const __nv_bfloat16* Qhg = g_qh + base + (size_t)qi * 128 * NHS;
    const __nv_bfloat16* Qlg = g_ql + base + (size_t)qi * 128 * NHS;
    const __nv_bfloat16* Khg = g_kh + base;
    const __nv_bfloat16* Klg = g_kl + base;
    const __half* Vg = g_vh + base;

    const uint32_t sb = (uint32_t)__cvta_generic_to_shared(su);
    const int lm = lane & 7, sel = lane >> 3;
    const int rowA = lm + ((sel & 1) << 3), colA = (sel & 2) << 1;
    const int rowB = lm + ((sel & 2) << 2), colB = (sel & 1) << 2;
    const uint32_t qH0 = sb + ((warp * 16 + rowA) * 36 + colA) * 4;
    const uint32_t qL0 = qH0 + 4608 * 4;
    const uint32_t kH0 = sb + 9216 * 4 + (rowB * 36 + colB) * 4;
    const uint32_t kL0 = kH0 + 1152 * 4;
    const uint32_t vH0 = sb + 11520 * 4 + (rowB * 20 + colB) * 4;
    const uint32_t pH0 = sb + 12800 * 4 + ((warp * 16 + rowA) * 20 + colA) * 4;

    {
        int r = tid >> 1, cc = (tid & 1) * 16;
#pragma unroll
        for (int j = 0; j < 4; j++) {
            int eo = (cc + 4 * j) * 2;
            *(uint4*)&sQh[r * 36 + cc + 4 * j] = *(const uint4*)(Qhg + r * NHS + eo);
            *(uint4*)&sQl[r * 36 + cc + 4 * j] = *(const uint4*)(Qlg + r * NHS + eo);
        }
    }

    float o[8][4];
#pragma unroll
    for (int i = 0; i < 8; i++)
#pragma unroll
        for (int j = 0; j < 4; j++) o[i][j] = 0.f;
    float mr[2] = {-1e30f, -1e30f}, lsum[2] = {0.f, 0.f};

    const int row0 = qi * 128 + warp * 16 + g;
    const int nkt = 4 * qi + 4;

    const int kr = tid >> 3, kc = (tid & 7) * 4;
    const int vd = tid & 63, vq = tid >> 6;
    uint4 rkh, rkl;
    __half rv0[4], rv1[4];
#define LD_KV(KT)                                                                  \
    {                                                                              \
        rkh = *(const uint4*)(Khg + (size_t)((KT) * 32 + kr) * NHS + kc * 2);      \
        rkl = *(const uint4*)(Klg + (size_t)((KT) * 32 + kr) * NHS + kc * 2);      \
        _Pragma("unroll") for (int i = 0; i < 4; i++) {                            \
            int kp = vq * 4 + i;                                                   \
            rv0[i] = Vg[(size_t)((KT) * 32 + 2 * kp) * NHS + vd];                  \
            rv1[i] = Vg[(size_t)((KT) * 32 + 2 * kp + 1) * NHS + vd];              \
        }                                                                          \
    }
    LD_KV(0);

    for (int kt = 0; kt < nkt; kt++) {
        __syncthreads();
        *(uint4*)&sKh[kr * 36 + kc] = rkh;
        *(uint4*)&sKl[kr * 36 + kc] = rkl;
        {
            uint4 vh4;
            __half2 t;
            t.x = rv0[0]; t.y = rv1[0]; vh4.x = *(uint32_t*)&t;
            t.x = rv0[1]; t.y = rv1[1]; vh4.y = *(uint32_t*)&t;
            t.x = rv0[2]; t.y = rv1[2]; vh4.z = *(uint32_t*)&t;
            t.x = rv0[3]; t.y = rv1[3]; vh4.w = *(uint32_t*)&t;
            *(uint4*)&sVh[vd * 20 + vq * 4] = vh4;
        }
        __syncthreads();
        if (kt + 1 < nkt) LD_KV(kt + 1);

        if (kt * 32 > qi * 128 + warp * 16 + 15) continue;

        // S = Q K^T (16x32 per warp), 3xBF16
        float s[4][4];
#pragma unroll
        for (int i = 0; i < 4; i++)
#pragma unroll
            for (int j = 0; j < 4; j++) s[i][j] = 0.f;

#pragma unroll
        for (int ks = 0; ks < 4; ks++) {
            const uint32_t ko = ks * 32;
            uint32_t qh[4], ql[4];
            ldsm4(qh, qH0 + ko);
            ldsm4(ql, qL0 + ko);
#pragma unroll
            for (int j = 0; j < 2; j++) {
                uint32_t kh[4], kl[4];
                ldsm4(kh, kH0 + ko + j * 2304);
                ldsm4(kl, kL0 + ko + j * 2304);
                mma16(s[2 * j],     qh, kh[0], kh[1]);
                mma16(s[2 * j],     ql, kh[0], kh[1]);
                mma16(s[2 * j],     qh, kl[0], kl[1]);
                mma16(s[2 * j + 1], qh, kh[2], kh[3]);
                mma16(s[2 * j + 1], ql, kh[2], kh[3]);
                mma16(s[2 * j + 1], qh, kl[2], kl[3]);
            }
        }

        if (kt * 32 + 31 > qi * 128 + warp * 16) {
#pragma unroll
            for (int nt = 0; nt < 4; nt++)
#pragma unroll
                for (int c = 0; c < 4; c++) {
                    int key = kt * 32 + nt * 8 + 2 * tg + (c & 1);
                    int rr = row0 + ((c & 2) ? 8 : 0);
                    if (key > rr) s[nt][c] = -1e30f;
                }
        }

#pragma unroll
        for (int r = 0; r < 2; r++) {
            const int cb = 2 * r;
            float mx = mr[r];
#pragma unroll
            for (int nt = 0; nt < 4; nt++)
                mx = fmaxf(mx, fmaxf(s[nt][cb], s[nt][cb + 1]));
            mx = fmaxf(mx, __shfl_xor_sync(0xffffffffu, mx, 1));
            mx = fmaxf(mx, __shfl_xor_sync(0xffffffffu, mx, 2));
            float alpha = __expf(mr[r] - mx);
            float rs = 0.f;
#pragma unroll
            for (int nt = 0; nt < 4; nt++) {
                float p0 = __expf(s[nt][cb] - mx);
                float p1 = __expf(s[nt][cb + 1] - mx);
                s[nt][cb] = p0; s[nt][cb + 1] = p1;
                rs += p0 + p1;
            }
            rs += __shfl_xor_sync(0xffffffffu, rs, 1);
            rs += __shfl_xor_sync(0xffffffffu, rs, 2);
            lsum[r] = lsum[r] * alpha + rs;
            mr[r] = mx;
#pragma unroll
            for (int nt = 0; nt < 8; nt++) {
                o[nt][cb] *= alpha; o[nt][cb + 1] *= alpha;
            }
        }

        // stage P fp16-rounded (warp-private rows)
#pragma unroll
        for (int nt = 0; nt < 4; nt++) {
            sPh[(warp * 16 + g) * 20 + nt * 4 + tg]     = pack_h2(s[nt][0], s[nt][1]);
            sPh[(warp * 16 + g + 8) * 20 + nt * 4 + tg] = pack_h2(s[nt][2], s[nt][3]);
        }
        __syncwarp();

        // O += P V : 1xFP16
#pragma unroll
        for (int ks = 0; ks < 2; ks++) {
            const uint32_t ko = ks * 32;
            uint32_t ph[4];
            ldsm4(ph, pH0 + ko);
#pragma unroll
            for (int j = 0; j < 4; j++) {
                uint32_t vh[4];
                ldsm4(vh, vH0 + ko + j * 1280);
                mma16h(o[2 * j],     ph, vh[0], vh[1]);
                mma16h(o[2 * j + 1], ph, vh[2], vh[3]);
            }
        }
    }

    // normalize + write attn-out fp16-rounded into g_xfh [B,T,C]
    const int bb = bh >> 4, hh = bh & 15;
    const float inv0 = 1.f / lsum[0], inv1 = 1.f / lsum[1];
#pragma unroll
    for (int nt = 0; nt < 8; nt++) {
        int col = hh * 64 + nt * 8 + 2 * tg;
        size_t off = (size_t)(bb * NT + row0) * NC + col;
        *(uint32_t*)(g_xfh + off)          = pack_h2(o[nt][0] * inv0, o[nt][1] * inv0);
        *(uint32_t*)(g_xfh + off + 8 * NC) = pack_h2(o[nt][2] * inv1, o[nt][3] * inv1);
    }
}

// ---------------- launcher --------------------------------------------------
extern "C" void kernel_launch(void* const* d_in, const int* in_sizes, int n_in,
                              void* d_out, int out_size)
{
    const float* x  = (const float*)d_in[0];
    const float* Wq = (const float*)d_in[1];
    const float* Wk = (const float*)d_in[2];
    const float* Wv = (const float*)d_in[3];
    const float* Wo = (const float*)d_in[4];
    const float* bo = (const float*)d_in[5];
    float* out = (float*)d_out;

    cudaFuncSetAttribute(gemm_bf16_kernel<0>, cudaFuncAttributeMaxDynamicSharedMemorySize, GEMM_SMEM);
    cudaFuncSetAttribute(gemm_bf16_kernel<1>, cudaFuncAttributeMaxDynamicSharedMemorySize, GEMM_SMEM);
    cudaFuncSetAttribute(gemm_bf16_kernel<2>, cudaFuncAttributeMaxDynamicSharedMemorySize, GEMM_SMEM);
    cudaFuncSetAttribute(flash_attn_kernel, cudaFuncAttributeMaxDynamicSharedMemorySize, FLASH_SMEM);

    // 1) pre-split x + weights (one fused launch)
    split_all_kernel<<<12288, 256>>>(x, Wq, Wk, Wv, Wo);

    // 2) Q/K projection (3xBF16) -> g_qh/ql, g_kh/kl
    gemm_bf16_kernel<0><<<dim3(16, 64), 256, GEMM_SMEM>>>(nullptr, nullptr);

    // 3) V projection (2xFP16) -> g_vh
    gemm_bf16_kernel<2><<<dim3(8, 64), 256, GEMM_SMEM>>>(nullptr, nullptr);

    // 4) causal flash attention (S 3xBF16, PV 1xFP16) -> g_xfh
    flash_attn_kernel<<<dim3(NT / 128, NB * NH), 256, FLASH_SMEM>>>();

    // 5) out projection (1xFP16) + bias -> d_out
    gemm_bf16_kernel<1><<<dim3(8, 64), 256, GEMM_SMEM>>>(bo, out);
}

// round 17
// speedup vs baseline: 1.3884x; 1.0166x over previous
#include <cuda_runtime.h>
#include <cuda_bf16.h>
#include <cuda_fp16.h>
#include <cstdint>

#define NB 4
#define NT 2048
#define NC 1024
#define NH 16
#define NHS 64

// ---------------- scratch (static device globals) ---------------------------
__device__ __half g_vh[(size_t)NB * NH * NT * NHS];   // V, fp16-rounded
__device__ __nv_bfloat16 g_qh[(size_t)NB * NH * NT * NHS];
__device__ __nv_bfloat16 g_ql[(size_t)NB * NH * NT * NHS];
__device__ __nv_bfloat16 g_kh[(size_t)NB * NH * NT * NHS];
__device__ __nv_bfloat16 g_kl[(size_t)NB * NH * NT * NHS];
__device__ __nv_bfloat16 g_xh[(size_t)NB * NT * NC];  // x bf16 hi/lo (QK path)
__device__ __nv_bfloat16 g_xl[(size_t)NB * NT * NC];
__device__ __half g_xfh[(size_t)NB * NT * NC];        // x fp16 hi/lo (V path); then attn-out fp16
__device__ __half g_xfl[(size_t)NB * NT * NC];
__device__ __nv_bfloat16 g_wh[(size_t)2 * NC * NC];   // Wq|Wk rows (bf16 split)
__device__ __nv_bfloat16 g_wl[(size_t)2 * NC * NC];
__device__ __half g_wvh[(size_t)NC * NC];             // Wv fp16-rounded
__device__ __half g_woh[(size_t)NC * NC];             // Wo fp16-rounded

// ---------------- helpers ---------------------------------------------------
__device__ __forceinline__ void mma16(float* d, const uint32_t* a, uint32_t b0, uint32_t b1) {
    asm volatile(
        "mma.sync.aligned.m16n8k16.row.col.f32.bf16.bf16.f32 "
        "{%0,%1,%2,%3}, {%4,%5,%6,%7}, {%8,%9}, {%0,%1,%2,%3};"
        : "+f"(d[0]), "+f"(d[1]), "+f"(d[2]), "+f"(d[3])
        : "r"(a[0]), "r"(a[1]), "r"(a[2]), "r"(a[3]), "r"(b0), "r"(b1));
}
__device__ __forceinline__ void mma16h(float* d, const uint32_t* a, uint32_t b0, uint32_t b1) {
    asm volatile(
        "mma.sync.aligned.m16n8k16.row.col.f32.f16.f16.f32 "
        "{%0,%1,%2,%3}, {%4,%5,%6,%7}, {%8,%9}, {%0,%1,%2,%3};"
        : "+f"(d[0]), "+f"(d[1]), "+f"(d[2]), "+f"(d[3])
        : "r"(a[0]), "r"(a[1]), "r"(a[2]), "r"(a[3]), "r"(b0), "r"(b1));
}
__device__ __forceinline__ void ldsm4(uint32_t* r, uint32_t addr) {
    asm volatile("ldmatrix.sync.aligned.m8n8.x4.shared.b16 {%0,%1,%2,%3}, [%4];"
                 : "=r"(r[0]), "=r"(r[1]), "=r"(r[2]), "=r"(r[3]) : "r"(addr));
}
__device__ __forceinline__ void split_pack(float a, float b, uint32_t& h, uint32_t& l) {
    __nv_bfloat16 ha = __float2bfloat16(a), hb = __float2bfloat16(b);
    __nv_bfloat162 th; th.x = ha; th.y = hb;
    h = *(uint32_t*)&th;
    __nv_bfloat162 tl;
    tl.x = __float2bfloat16(a - __bfloat162float(ha));
    tl.y = __float2bfloat16(b - __bfloat162float(hb));
    l = *(uint32_t*)&tl;
}
__device__ __forceinline__ void split_pack_h(float a, float b, uint32_t& h, uint32_t& l) {
    __half ha = __float2half_rn(a), hb = __float2half_rn(b);
    __half2 th; th.x = ha; th.y = hb;
    h = *(uint32_t*)&th;
    __half2 tl;
    tl.x = __float2half_rn(a - __half2float(ha));
    tl.y = __float2half_rn(b - __half2float(hb));
    l = *(uint32_t*)&tl;
}
__device__ __forceinline__ uint32_t pack_h2(float a, float b) {
    __half2 t; t.x = __float2half_rn(a); t.y = __float2half_rn(b);
    return *(uint32_t*)&t;
}
#define CPA16(dst, src) \
    asm volatile("cp.async.cg.shared.global [%0], [%1], 16;" :: "r"(dst), "l"(src))
#define CPA_COMMIT() asm volatile("cp.async.commit_group;" ::: "memory")
#define CPA_WAIT1() asm volatile("cp.async.wait_group 1;" ::: "memory")
#define CPA_WAIT0() asm volatile("cp.async.wait_group 0;" ::: "memory")

// ---------------- fused split ------------------------------------------------
__global__ void __launch_bounds__(256) split_all_kernel(
    const float* __restrict__ x,  const float* __restrict__ Wq,
    const float* __restrict__ Wk, const float* __restrict__ Wv,
    const float* __restrict__ Wo)
{
    const size_t XN = (size_t)NB * NT * NC;   // 8M
    const size_t WN = (size_t)NC * NC;        // 1M
    size_t i = ((size_t)blockIdx.x * 256 + threadIdx.x) * 4;
    if (i < XN) {
        float4 v = *(const float4*)(x + i);
        uint32_t h0, l0, h1, l1;
        split_pack(v.x, v.y, h0, l0); split_pack(v.z, v.w, h1, l1);
        *(uint32_t*)(g_xh + i) = h0; *(uint32_t*)(g_xh + i + 2) = h1;
        *(uint32_t*)(g_xl + i) = l0; *(uint32_t*)(g_xl + i + 2) = l1;
        split_pack_h(v.x, v.y, h0, l0); split_pack_h(v.z, v.w, h1, l1);
        *(uint32_t*)(g_xfh + i) = h0; *(uint32_t*)(g_xfh + i + 2) = h1;
        *(uint32_t*)(g_xfl + i) = l0; *(uint32_t*)(g_xfl + i + 2) = l1;
    } else if (i < XN + 2 * WN) {
        const float* src = (i < XN + WN) ? Wq : Wk;
        size_t off = (i < XN + WN) ? (i - XN) : (i - XN - WN);
        size_t dsto = (i < XN + WN) ? off : off + WN;
        float4 v = *(const float4*)(src + off);
        uint32_t h0, l0, h1, l1;
        split_pack(v.x, v.y, h0, l0); split_pack(v.z, v.w, h1, l1);
        *(uint32_t*)(g_wh + dsto) = h0; *(uint32_t*)(g_wh + dsto + 2) = h1;
        *(uint32_t*)(g_wl + dsto) = l0; *(uint32_t*)(g_wl + dsto + 2) = l1;
    } else {
        const float* src = (i < XN + 3 * WN) ? Wv : Wo;
        __half* dst = (i < XN + 3 * WN) ? g_wvh : g_woh;
        size_t off = (i < XN + 3 * WN) ? (i - XN - 2 * WN) : (i - XN - 3 * WN);
        float4 v = *(const float4*)(src + off);
        *(uint32_t*)(dst + off)     = pack_h2(v.x, v.y);
        *(uint32_t*)(dst + off + 2) = pack_h2(v.z, v.w);
    }
}

// ---------------- GEMM (128x128 tile, 2-stage cp.async, 2 CTA/SM) -----------
// MODE 0: QK, 3xBF16; scatter q (x8) / k, bf16 split.
// MODE 2: V,  2xFP16 (x fp16 pair exact x Wv fp16 rounded) -> g_vh fp16.
// MODE 1: out-proj, 1xFP16 + bias -> Out f32.
static constexpr int G_STG = 10240;
static constexpr int GEMM_SMEM = 2 * G_STG * 4;  // 81920 B

template <int MODE>
__global__ void __launch_bounds__(256, 2) gemm_bf16_kernel(
    const float* __restrict__ bias, float* __restrict__ Out)
{
    extern __shared__ uint32_t su[];

    const int tid = threadIdx.x;
    const int warp = tid >> 5, lane = tid & 31;
    const int g = lane >> 2, tg = lane & 3;
    const int wm = warp >> 2, wn = warp & 3;
    const int m0 = blockIdx.y * 128;
    const int n0 = blockIdx.x * 128;

    const __nv_bfloat16 *Ah, *Al = nullptr, *Bh, *Bl = nullptr;
    if (MODE == 0) { Ah = g_xh; Al = g_xl; Bh = g_wh; Bl = g_wl; }
    else if (MODE == 2) {
        Ah = (const __nv_bfloat16*)g_xfh; Al = (const __nv_bfloat16*)g_xfl;
        Bh = (const __nv_bfloat16*)g_wvh;
    } else {
        Ah = (const __nv_bfloat16*)g_xfh;
        Bh = (const __nv_bfloat16*)g_woh;
    }

    float acc[4][4][4];
#pragma unroll
    for (int a = 0; a < 4; a++)
#pragma unroll
        for (int b = 0; b < 4; b++)
#pragma unroll
            for (int c = 0; c < 4; c++) acc[a][b][c] = 0.f;

    const int lr = tid >> 1;
    const int lc = (tid & 1) * 8;
    const __nv_bfloat16* pA_h = Ah + (size_t)(m0 + lr) * NC + lc * 2;
    const __nv_bfloat16* pA_l = (MODE != 1) ? Al + (size_t)(m0 + lr) * NC + lc * 2 : nullptr;
    const __nv_bfloat16* pB_h = Bh + (size_t)(n0 + lr) * NC + lc * 2;
    const __nv_bfloat16* pB_l = (MODE == 0) ? Bl + (size_t)(n0 + lr) * NC + lc * 2 : nullptr;
    const uint32_t sb = (uint32_t)__cvta_generic_to_shared(su);
    const uint32_t sdst = sb + (lr * 20 + lc) * 4;

    const int lm = lane & 7, sel = lane >> 3;
    const int rowA = lm + ((sel & 1) << 3), colA = (sel & 2) << 1;
    const int rowB = lm + ((sel & 2) << 2), colB = (sel & 1) << 2;
    const uint32_t aH0 = sb + ((wm * 64 + rowA) * 20 + colA) * 4;
    const uint32_t aL0 = aH0 + 2560 * 4;
    const uint32_t bH0 = sb + 5120 * 4 + ((wn * 32 + rowB) * 20 + colB) * 4;
    const uint32_t bL0 = bH0 + 2560 * 4;

#define G_LOAD(S, KT)                                                          \
    {                                                                          \
        uint32_t d0 = sdst + (S) * (G_STG * 4);                                \
        CPA16(d0,                 pA_h + (KT));                                \
        CPA16(d0 + 16,            pA_h + (KT) + 8);                            \
        if (MODE != 1) {                                                       \
            CPA16(d0 + 2560 * 4,      pA_l + (KT));                            \
            CPA16(d0 + 2560 * 4 + 16, pA_l + (KT) + 8);                        \
        }                                                                      \
        CPA16(d0 + 5120 * 4,      pB_h + (KT));                                \
        CPA16(d0 + 5120 * 4 + 16, pB_h + (KT) + 8);                            \
        if (MODE == 0) {                                                       \
            CPA16(d0 + 7680 * 4,      pB_l + (KT));                            \
            CPA16(d0 + 7680 * 4 + 16, pB_l + (KT) + 8);                        \
        }                                                                      \
        CPA_COMMIT();                                                          \
    }

    G_LOAD(0, 0);

    for (int c = 0; c < 32; c++) {
        if (c < 31) { G_LOAD((c + 1) & 1, (c + 1) * 32); CPA_WAIT1(); }
        else        { CPA_WAIT0(); }
        __syncthreads();
        const uint32_t stg = (c & 1) * (G_STG * 4);

#pragma unroll
        for (int ks = 0; ks < 2; ks++) {
            const uint32_t ko = stg + ks * 32;
            uint32_t ah[4][4], al[4][4];
#pragma unroll
            for (int mt = 0; mt < 4; mt++) {
                ldsm4(ah[mt], aH0 + ko + mt * 1280);
                if (MODE != 1) ldsm4(al[mt], aL0 + ko + mt * 1280);
            }
#pragma unroll
            for (int j = 0; j < 2; j++) {
                uint32_t bh[4];
                ldsm4(bh, bH0 + ko + j * 1280);
                if (MODE == 0) {
                    uint32_t bl[4];
                    ldsm4(bl, bL0 + ko + j * 1280);
#pragma unroll
                    for (int mt = 0; mt < 4; mt++) {
                        mma16(acc[mt][2 * j],     ah[mt], bh[0], bh[1]);
                        mma16(acc[mt][2 * j],     al[mt], bh[0], bh[1]);
                        mma16(acc[mt][2 * j],     ah[mt], bl[0], bl[1]);
                        mma16(acc[mt][2 * j + 1], ah[mt], bh[2], bh[3]);
                        mma16(acc[mt][2 * j + 1], al[mt], bh[2], bh[3]);
                        mma16(acc[mt][2 * j + 1], ah[mt], bl[2], bl[3]);
                    }
                } else if (MODE == 2) {
#pragma unroll
                    for (int mt = 0; mt < 4; mt++) {
                        mma16h(acc[mt][2 * j],     ah[mt], bh[0], bh[1]);
                        mma16h(acc[mt][2 * j],     al[mt], bh[0], bh[1]);
                        mma16h(acc[mt][2 * j + 1], ah[mt], bh[2], bh[3]);
                        mma16h(acc[mt][2 * j + 1], al[mt], bh[2], bh[3]);
                    }
                } else {
#pragma unroll
                    for (int mt = 0; mt < 4; mt++) {
                        mma16h(acc[mt][2 * j],     ah[mt], bh[0], bh[1]);
                        mma16h(acc[mt][2 * j + 1], ah[mt], bh[2], bh[3]);
                    }
                }
            }
        }
        __syncthreads();
    }

#pragma unroll
    for (int mt = 0; mt < 4; mt++) {
        int row = m0 + wm * 64 + mt * 16 + g;
#pragma unroll
        for (int nt = 0; nt < 4; nt++) {
            int colg = n0 + wn * 32 + nt * 8 + 2 * tg;
            int b = row >> 11, t = row & (NT - 1);
            if (MODE == 0) {
                int sl = colg >> 10, cc = colg & 1023;
                int h = cc >> 6, d = cc & 63;
                size_t off = (((size_t)(b * NH + h) * NT) + t) * NHS + d;
                float sc = (sl == 0) ? 8.f : 1.f;
                __nv_bfloat16* dh = (sl == 0) ? g_qh : g_kh;
                __nv_bfloat16* dl = (sl == 0) ? g_ql : g_kl;
                uint32_t ph, pl;
                split_pack(acc[mt][nt][0] * sc, acc[mt][nt][1] * sc, ph, pl);
                *(uint32_t*)(dh + off) = ph;
                *(uint32_t*)(dl + off) = pl;
                split_pack(acc[mt][nt][2] * sc, acc[mt][nt][3] * sc, ph, pl);
                *(uint32_t*)(dh + off + 8 * NHS) = ph;
                *(uint32_t*)(dl + off + 8 * NHS) = pl;
            } else if (MODE == 2) {
                int h = colg >> 6, d = colg & 63;
                size_t off = (((size_t)(b * NH + h) * NT) + t) * NHS + d;
                *(uint32_t*)(g_vh + off) = pack_h2(acc[mt][nt][0], acc[mt][nt][1]);
                *(uint32_t*)(g_vh + off + 8 * NHS) = pack_h2(acc[mt][nt][2], acc[mt][nt][3]);
            } else {
                float2 bv = *(const float2*)(bias + colg);
                *(float2*)(Out + (size_t)row * NC + colg) =
                    make_float2(acc[mt][nt][0] + bv.x, acc[mt][nt][1] + bv.y);
                *(float2*)(Out + (size_t)(row + 8) * NC + colg) =
                    make_float2(acc[mt][nt][2] + bv.x, acc[mt][nt][3] + bv.y);
            }
        }
    }
}

// ---------------- flash attention: KSTEP=64, S 3xBF16, PV 1xFP16 -------------
// smem (u32): Qh 0..4608 | Ql 4608 | K stages 9216 + s*4608 (kh 2304, kl 2304)
//             | Vh 18432 (64x36) | Ph 20736 (128x36)   total 25344 u32
static constexpr int FLASH_SMEM = 25344 * 4;  // 101376 B

__global__ void __launch_bounds__(256, 2) flash_attn_kernel()
{
    extern __shared__ uint32_t su[];
    uint32_t* sQh = su;
    uint32_t* sQl = su + 4608;
    uint32_t* sVh = su + 18432;

    const int tid = threadIdx.x;
    const int warp = tid >> 5, lane = tid & 31;
    const int g = lane >> 2, tg = lane & 3;
    const int qi = (int)gridDim.x - 1 - (int)blockIdx.x;   // longest first
    const int bh = blockIdx.y;

    const size_t base = (size_t)bh * NT * NHS;
    const __nv_bfloat16* Qhg = g_qh + base + (size_t)qi * 128 * NHS;
    const __nv_bfloat16* Qlg = g_ql + base + (size_t)qi * 128 * NHS;
    const __nv_bfloat16* Khg = g_kh + base;
    const __nv_bfloat16* Klg = g_kl + base;
    const __half* Vg = g_vh + base;

    const uint32_t sb = (uint32_t)__cvta_generic_to_shared(su);
    const int lm = lane & 7, sel = lane >> 3;
    const int rowA = lm + ((sel & 1) << 3), colA = (sel & 2) << 1;
    const int rowB = lm + ((sel & 2) << 2), colB = (sel & 1) << 2;
    const uint32_t qH0 = sb + ((warp * 16 + rowA) * 36 + colA) * 4;
    const uint32_t qL0 = qH0 + 4608 * 4;
    const uint32_t kS0 = sb + 9216 * 4 + ((rowB) * 36 + colB) * 4;  // + stage*4608*4; kl +2304*4
    const uint32_t vH0 = sb + 18432 * 4 + ((rowB) * 36 + colB) * 4;
    const uint32_t pH0 = sb + 20736 * 4 + ((warp * 16 + rowA) * 36 + colA) * 4;
    uint32_t* sPh = su + 20736;

    // load Q tile
    {
        int r = tid >> 1, cc = (tid & 1) * 16;
#pragma unroll
        for (int j = 0; j < 4; j++) {
            int eo = (cc + 4 * j) * 2;
            *(uint4*)&sQh[r * 36 + cc + 4 * j] = *(const uint4*)(Qhg + r * NHS + eo);
            *(uint4*)&sQl[r * 36 + cc + 4 * j] = *(const uint4*)(Qlg + r * NHS + eo);
        }
    }

    float o[8][4];
#pragma unroll
    for (int i = 0; i < 8; i++)
#pragma unroll
        for (int j = 0; j < 4; j++) o[i][j] = 0.f;
    float mr[2] = {-1e30f, -1e30f}, lsum[2] = {0.f, 0.f};

    const int row0 = qi * 128 + warp * 16 + g;
    const int nkt = 2 * qi + 2;     // 64-key steps

    // K loader (cp.async): 64 rows x 32 u32 per array
    const int kr = tid >> 2, kc = (tid & 3) * 8;
    // V loader (register gather + transpose): 8 key-pairs per thread
    const int vd = tid & 63, vq = tid >> 6;
    __half rv0[8], rv1[8];

#define LD_K_ASYNC(KT, S)                                                          \
    {                                                                              \
        const __nv_bfloat16* ph = Khg + (size_t)((KT) * 64 + kr) * NHS + kc * 2;   \
        const __nv_bfloat16* pl = Klg + (size_t)((KT) * 64 + kr) * NHS + kc * 2;   \
        uint32_t d = sb + (9216 + (S) * 4608 + kr * 36 + kc) * 4;                  \
        CPA16(d, ph); CPA16(d + 16, ph + 8);                                       \
        CPA16(d + 2304 * 4, pl); CPA16(d + 2304 * 4 + 16, pl + 8);                 \
        CPA_COMMIT();                                                              \
    }
#define LD_V(KT)                                                                   \
    {                                                                              \
        _Pragma("unroll") for (int i = 0; i < 8; i++) {                            \
            int kp = vq * 8 + i;                                                   \
            rv0[i] = Vg[(size_t)((KT) * 64 + 2 * kp) * NHS + vd];                  \
            rv1[i] = Vg[(size_t)((KT) * 64 + 2 * kp + 1) * NHS + vd];              \
        }                                                                          \
    }

    LD_K_ASYNC(0, 0);
    LD_V(0);

    for (int kt = 0; kt < nkt; kt++) {
        __syncthreads();               // V smem reusable
        {
            uint4 a, b;
            __half2 t;
            t.x = rv0[0]; t.y = rv1[0]; a.x = *(uint32_t*)&t;
            t.x = rv0[1]; t.y = rv1[1]; a.y = *(uint32_t*)&t;
            t.x = rv0[2]; t.y = rv1[2]; a.z = *(uint32_t*)&t;
            t.x = rv0[3]; t.y = rv1[3]; a.w = *(uint32_t*)&t;
            t.x = rv0[4]; t.y = rv1[4]; b.x = *(uint32_t*)&t;
            t.x = rv0[5]; t.y = rv1[5]; b.y = *(uint32_t*)&t;
            t.x = rv0[6]; t.y = rv1[6]; b.z = *(uint32_t*)&t;
            t.x = rv0[7]; t.y = rv1[7]; b.w = *(uint32_t*)&t;
            *(uint4*)&sVh[vd * 36 + vq * 8]     = a;
            *(uint4*)&sVh[vd * 36 + vq * 8 + 4] = b;
        }
        CPA_WAIT0();                   // K stage (kt&1) landed
        __syncthreads();               // V + K visible to all
        if (kt + 1 < nkt) { LD_K_ASYNC(kt + 1, (kt + 1) & 1); LD_V(kt + 1); }

        if (kt * 64 > qi * 128 + warp * 16 + 15) continue;  // fully masked

        const uint32_t kH0 = kS0 + (kt & 1) * 4608 * 4;
        const uint32_t kL0 = kH0 + 2304 * 4;

        // S = Q K^T (16x64 per warp), 3xBF16
        float s[8][4];
#pragma unroll
        for (int i = 0; i < 8; i++)
#pragma unroll
            for (int j = 0; j < 4; j++) s[i][j] = 0.f;

#pragma unroll
        for (int ks = 0; ks < 4; ks++) {
            const uint32_t ko = ks * 32;
            uint32_t qh[4], ql[4];
            ldsm4(qh, qH0 + ko);
            ldsm4(ql, qL0 + ko);
#pragma unroll
            for (int j = 0; j < 4; j++) {
                uint32_t kh[4], kl[4];
                ldsm4(kh, kH0 + ko + j * 2304);
                ldsm4(kl, kL0 + ko + j * 2304);
                mma16(s[2 * j],     qh, kh[0], kh[1]);
                mma16(s[2 * j],     ql, kh[0], kh[1]);
                mma16(s[2 * j],     qh, kl[0], kl[1]);
                mma16(s[2 * j + 1], qh, kh[2], kh[3]);
                mma16(s[2 * j + 1], ql, kh[2], kh[3]);
                mma16(s[2 * j + 1], qh, kl[2], kl[3]);
            }
        }

        // causal mask
        if (kt * 64 + 63 > qi * 128 + warp * 16) {
#pragma unroll
            for (int nt = 0; nt < 8; nt++)
#pragma unroll
                for (int c = 0; c < 4; c++) {
                    int key = kt * 64 + nt * 8 + 2 * tg + (c & 1);
                    int rr = row0 + ((c & 2) ? 8 : 0);
                    if (key > rr) s[nt][c] = -1e30f;
                }
        }

        // online softmax (rows g, g+8)
#pragma unroll
        for (int r = 0; r < 2; r++) {
            const int cb = 2 * r;
            float mx = mr[r];
#pragma unroll
            for (int nt = 0; nt < 8; nt++)
                mx = fmaxf(mx, fmaxf(s[nt][cb], s[nt][cb + 1]));
            mx = fmaxf(mx, __shfl_xor_sync(0xffffffffu, mx, 1));
            mx = fmaxf(mx, __shfl_xor_sync(0xffffffffu, mx, 2));
            float alpha = __expf(mr[r] - mx);
            float rs = 0.f;
#pragma unroll
            for (int nt = 0; nt < 8; nt++) {
                float p0 = __expf(s[nt][cb] - mx);
                float p1 = __expf(s[nt][cb + 1] - mx);
                s[nt][cb] = p0; s[nt][cb + 1] = p1;
                rs += p0 + p1;
            }
            rs += __shfl_xor_sync(0xffffffffu, rs, 1);
            rs += __shfl_xor_sync(0xffffffffu, rs, 2);
            lsum[r] = lsum[r] * alpha + rs;
            mr[r] = mx;
#pragma unroll
            for (int nt = 0; nt < 8; nt++) {
                o[nt][cb] *= alpha; o[nt][cb + 1] *= alpha;
            }
        }

        // stage P fp16-rounded (warp-private rows)
#pragma unroll
        for (int nt = 0; nt < 8; nt++) {
            sPh[(warp * 16 + g) * 36 + nt * 4 + tg]     = pack_h2(s[nt][0], s[nt][1]);
            sPh[(warp * 16 + g + 8) * 36 + nt * 4 + tg] = pack_h2(s[nt][2], s[nt][3]);
        }
        __syncwarp();

        // O += P V : 1xFP16 (k-dim 64)
#pragma unroll
        for (int ks = 0; ks < 4; ks++) {
            const uint32_t ko = ks * 32;
            uint32_t ph[4];
            ldsm4(ph, pH0 + ko);
#pragma unroll
            for (int j = 0; j < 4; j++) {
                uint32_t vh[4];
                ldsm4(vh, vH0 + ko + j * 2304);
                mma16h(o[2 * j],     ph, vh[0], vh[1]);
                mma16h(o[2 * j + 1], ph, vh[2], vh[3]);
            }
        }
    }

    // normalize + write attn-out fp16-rounded into g_xfh [B,T,C]
    const int bb = bh >> 4, hh = bh & 15;
    const float inv0 = 1.f / lsum[0], inv1 = 1.f / lsum[1];
#pragma unroll
    for (int nt = 0; nt < 8; nt++) {
        int col = hh * 64 + nt * 8 + 2 * tg;
        size_t off = (size_t)(bb * NT + row0) * NC + col;
        *(uint32_t*)(g_xfh + off)          = pack_h2(o[nt][0] * inv0, o[nt][1] * inv0);
        *(uint32_t*)(g_xfh + off + 8 * NC) = pack_h2(o[nt][2] * inv1, o[nt][3] * inv1);
    }
}

// ---------------- launcher --------------------------------------------------
extern "C" void kernel_launch(void* const* d_in, const int* in_sizes, int n_in,
                              void* d_out, int out_size)
{
    const float* x  = (const float*)d_in[0];
    const float* Wq = (const float*)d_in[1];
    const float* Wk = (const float*)d_in[2];
    const float* Wv = (const float*)d_in[3];
    const float* Wo = (const float*)d_in[4];
    const float* bo = (const float*)d_in[5];
    float* out = (float*)d_out;

    cudaFuncSetAttribute(gemm_bf16_kernel<0>, cudaFuncAttributeMaxDynamicSharedMemorySize, GEMM_SMEM);
    cudaFuncSetAttribute(gemm_bf16_kernel<1>, cudaFuncAttributeMaxDynamicSharedMemorySize, GEMM_SMEM);
    cudaFuncSetAttribute(gemm_bf16_kernel<2>, cudaFuncAttributeMaxDynamicSharedMemorySize, GEMM_SMEM);
    cudaFuncSetAttribute(flash_attn_kernel, cudaFuncAttributeMaxDynamicSharedMemorySize, FLASH_SMEM);

    // 1) pre-split x + weights
    split_all_kernel<<<12288, 256>>>(x, Wq, Wk, Wv, Wo);

    // 2) Q/K projection (3xBF16) -> g_qh/ql, g_kh/kl
    gemm_bf16_kernel<0><<<dim3(16, 64), 256, GEMM_SMEM>>>(nullptr, nullptr);

    // 3) V projection (2xFP16) -> g_vh
    gemm_bf16_kernel<2><<<dim3(8, 64), 256, GEMM_SMEM>>>(nullptr, nullptr);

    // 4) causal flash attention (KSTEP=64, S 3xBF16, PV 1xFP16) -> g_xfh
    flash_attn_kernel<<<dim3(NT / 128, NB * NH), 256, FLASH_SMEM>>>();

    // 5) out projection (1xFP16) + bias -> d_out
    gemm_bf16_kernel<1><<<dim3(8, 64), 256, GEMM_SMEM>>>(bo, out);
}